// round 1
// baseline (speedup 1.0000x reference)
#include <cuda_runtime.h>

// Problem constants
#define N_TOK   384
#define WDIM    512
#define EMB     1024          // 2*WDIM
#define HDIM    1024
#define NSPAN   73920         // 384*385/2
#define MTILES  578           // ceil(NSPAN/128)
#define NSPAN_PAD (MTILES*128) // 73984

// Scratch (static device memory; no allocations allowed)
__device__ float g_pref[(N_TOK + 1) * EMB];      // prefix sums of embeddings
__device__ float g_P[(N_TOK + 1) * HDIM];        // P = pref @ W_dan1
__device__ float g_h2[(size_t)NSPAN * HDIM];     // output of DAN layer 2 (302 MB)
__device__ int   g_si[NSPAN_PAD];
__device__ int   g_sj[NSPAN_PAD];
__device__ float g_wf[3 * HDIM];                 // per-column feat weight sums (len,i,end)
__device__ float g_part[(size_t)8 * NSPAN_PAD];  // per-column-block partial scores

// ---------------------------------------------------------------------------
// Kernel 1: embedding prefix sums. 1024 threads, one per column.
// pref[t+1][c] = sum_{u<=t} emb[u][c],  emb = concat(We_pos[pos], We_wrd[sent])
// ---------------------------------------------------------------------------
__global__ void k_pref(const int* __restrict__ sent, const int* __restrict__ pos,
                       const float* __restrict__ We_wrd, const float* __restrict__ We_pos)
{
    int c = blockIdx.x * blockDim.x + threadIdx.x;   // 0..1023
    if (c >= EMB) return;
    bool isPos = (c < WDIM);
    const float* base = isPos ? (We_pos + c) : (We_wrd + (c - WDIM));
    const int*   idx  = isPos ? pos : sent;
    float run = 0.f;
    g_pref[c] = 0.f;
    #pragma unroll 4
    for (int t = 0; t < N_TOK; ++t) {
        run += base[(size_t)idx[t] * WDIM];
        g_pref[(t + 1) * EMB + c] = run;
    }
}

// ---------------------------------------------------------------------------
// Kernel 2: span index tables (triu_indices order), pad region zeroed.
// ---------------------------------------------------------------------------
__global__ void k_spans()
{
    int i = blockIdx.x;                              // 0..383
    int base = i * N_TOK - (i * (i - 1)) / 2;
    for (int j = i + threadIdx.x; j < N_TOK; j += blockDim.x) {
        int s = base + (j - i);
        g_si[s] = i;
        g_sj[s] = j;
    }
    if (blockIdx.x == 0) {
        for (int s = NSPAN + threadIdx.x; s < NSPAN_PAD; s += blockDim.x) {
            g_si[s] = 0;
            g_sj[s] = 0;
        }
    }
}

// ---------------------------------------------------------------------------
// Kernel 3: fold feats into per-column weight sums.
// feats = repeat([len, start, end], 16) -> rows 1024..1039 / 1040..1055 / 1056..1071 of W_s1
// ---------------------------------------------------------------------------
__global__ void k_wfeat(const float* __restrict__ W_s1)
{
    int n = blockIdx.x * blockDim.x + threadIdx.x;   // 0..1023
    if (n >= HDIM) return;
    float sl = 0.f, si = 0.f, se = 0.f;
    #pragma unroll
    for (int r = 0; r < 16; ++r) {
        sl += W_s1[(HDIM +      r) * HDIM + n];
        si += W_s1[(HDIM + 16 + r) * HDIM + n];
        se += W_s1[(HDIM + 32 + r) * HDIM + n];
    }
    g_wf[n] = sl;
    g_wf[HDIM + n] = si;
    g_wf[2 * HDIM + n] = se;
}

// ---------------------------------------------------------------------------
// Kernel 4: small GEMM  P = pref @ W_dan1   ([385,1024] x [1024,1024])
// 32x32 tiles, 256 threads, 2x2 per thread.
// ---------------------------------------------------------------------------
__global__ void k_gemmP(const float* __restrict__ W)
{
    __shared__ float As[32][33];
    __shared__ float Bs[32][33];
    int tid = threadIdx.x;
    int tx = tid % 16, ty = tid / 16;
    int m0 = blockIdx.x * 32, n0 = blockIdx.y * 32;
    float acc00 = 0.f, acc01 = 0.f, acc10 = 0.f, acc11 = 0.f;

    for (int kk = 0; kk < EMB; kk += 32) {
        for (int e = tid; e < 32 * 32; e += 256) {
            int r = e / 32, c = e % 32;
            int gm = m0 + r;
            As[r][c] = (gm <= N_TOK) ? g_pref[gm * EMB + kk + c] : 0.f;
            Bs[r][c] = W[(kk + r) * HDIM + n0 + c];
        }
        __syncthreads();
        #pragma unroll
        for (int k = 0; k < 32; ++k) {
            float a0 = As[ty * 2][k], a1 = As[ty * 2 + 1][k];
            float b0 = Bs[k][tx * 2], b1 = Bs[k][tx * 2 + 1];
            acc00 = fmaf(a0, b0, acc00);
            acc01 = fmaf(a0, b1, acc01);
            acc10 = fmaf(a1, b0, acc10);
            acc11 = fmaf(a1, b1, acc11);
        }
        __syncthreads();
    }
    int gm0 = m0 + ty * 2, gn = n0 + tx * 2;
    if (gm0     <= N_TOK) { g_P[ gm0      * HDIM + gn] = acc00; g_P[ gm0      * HDIM + gn + 1] = acc01; }
    if (gm0 + 1 <= N_TOK) { g_P[(gm0 + 1) * HDIM + gn] = acc10; g_P[(gm0 + 1) * HDIM + gn + 1] = acc11; }
}

// ---------------------------------------------------------------------------
// Kernel 5: GEMM2 (fused).  h2 = relu( h1 @ W_dan2 + b2 )
// with h1[s,k] = relu( (P[end_s][k]-P[i_s][k]) * invlen_s + b1[k] ) computed on the fly.
// 128x128x8 tile, 256 threads, 8x8 per thread (strided 4+4 micro-tile).
// ---------------------------------------------------------------------------
__global__ __launch_bounds__(256, 2)
void k_gemm2(const float* __restrict__ W_dan2,
             const float* __restrict__ b_dan1,
             const float* __restrict__ b_dan2)
{
    __shared__ __align__(16) float sh[2048];
    float* As = sh;          // [8][128]
    float* Bs = sh + 1024;   // [8][128]

    int tid = threadIdx.x;
    int tx = tid % 16, ty = tid / 16;
    int m0 = blockIdx.x * 128, n0 = blockIdx.y * 128;

    // A-load assignment: row lm, k-offset 4*lkh
    int lm  = tid & 127;
    int lkh = tid >> 7;
    int s = m0 + lm; if (s >= NSPAN) s = NSPAN - 1;
    int i_ = g_si[s], j_ = g_sj[s];
    float invlen = 1.0f / (float)(j_ - i_ + 1);
    const float* Pe = g_P + (j_ + 1) * HDIM;
    const float* Pi = g_P + i_ * HDIM;

    // B-load assignment
    int br = tid >> 5;
    int bc = (tid & 31) << 2;

    float acc[8][8];
    #pragma unroll
    for (int a = 0; a < 8; ++a)
        #pragma unroll
        for (int b = 0; b < 8; ++b) acc[a][b] = 0.f;

    for (int kk = 0; kk < HDIM; kk += 8) {
        // A tile (fused h1 compute)
        {
            const float4 pe = *(const float4*)(Pe + kk + lkh * 4);
            const float4 pi = *(const float4*)(Pi + kk + lkh * 4);
            const float4 bb = *(const float4*)(b_dan1 + kk + lkh * 4);
            float v0 = fmaxf(fmaf(pe.x - pi.x, invlen, bb.x), 0.f);
            float v1 = fmaxf(fmaf(pe.y - pi.y, invlen, bb.y), 0.f);
            float v2 = fmaxf(fmaf(pe.z - pi.z, invlen, bb.z), 0.f);
            float v3 = fmaxf(fmaf(pe.w - pi.w, invlen, bb.w), 0.f);
            As[(lkh * 4 + 0) * 128 + lm] = v0;
            As[(lkh * 4 + 1) * 128 + lm] = v1;
            As[(lkh * 4 + 2) * 128 + lm] = v2;
            As[(lkh * 4 + 3) * 128 + lm] = v3;
        }
        // B tile
        *(float4*)(Bs + br * 128 + bc) = *(const float4*)(W_dan2 + (kk + br) * HDIM + n0 + bc);
        __syncthreads();

        #pragma unroll
        for (int k = 0; k < 8; ++k) {
            float a[8], b[8];
            float4 t;
            t = *(const float4*)(As + k * 128 + (ty << 2));      a[0]=t.x; a[1]=t.y; a[2]=t.z; a[3]=t.w;
            t = *(const float4*)(As + k * 128 + (ty << 2) + 64); a[4]=t.x; a[5]=t.y; a[6]=t.z; a[7]=t.w;
            t = *(const float4*)(Bs + k * 128 + (tx << 2));      b[0]=t.x; b[1]=t.y; b[2]=t.z; b[3]=t.w;
            t = *(const float4*)(Bs + k * 128 + (tx << 2) + 64); b[4]=t.x; b[5]=t.y; b[6]=t.z; b[7]=t.w;
            #pragma unroll
            for (int ii = 0; ii < 8; ++ii)
                #pragma unroll
                for (int jj = 0; jj < 8; ++jj)
                    acc[ii][jj] = fmaf(a[ii], b[jj], acc[ii][jj]);
        }
        __syncthreads();
    }

    // Epilogue: relu(acc + b2) -> g_h2
    float4 bn0 = *(const float4*)(b_dan2 + n0 + (tx << 2));
    float4 bn1 = *(const float4*)(b_dan2 + n0 + (tx << 2) + 64);
    float cb[8] = {bn0.x, bn0.y, bn0.z, bn0.w, bn1.x, bn1.y, bn1.z, bn1.w};
    #pragma unroll
    for (int ri = 0; ri < 8; ++ri) {
        int r = (ri < 4) ? ((ty << 2) + ri) : (64 + (ty << 2) + ri - 4);
        int gs = m0 + r;
        if (gs < NSPAN) {
            float4 o0, o1;
            o0.x = fmaxf(acc[ri][0] + cb[0], 0.f);
            o0.y = fmaxf(acc[ri][1] + cb[1], 0.f);
            o0.z = fmaxf(acc[ri][2] + cb[2], 0.f);
            o0.w = fmaxf(acc[ri][3] + cb[3], 0.f);
            o1.x = fmaxf(acc[ri][4] + cb[4], 0.f);
            o1.y = fmaxf(acc[ri][5] + cb[5], 0.f);
            o1.z = fmaxf(acc[ri][6] + cb[6], 0.f);
            o1.w = fmaxf(acc[ri][7] + cb[7], 0.f);
            *(float4*)(g_h2 + (size_t)gs * HDIM + n0 + (tx << 2))      = o0;
            *(float4*)(g_h2 + (size_t)gs * HDIM + n0 + (tx << 2) + 64) = o1;
        }
    }
}

// ---------------------------------------------------------------------------
// Kernel 6: GEMM3 (fused epilogue).  Per column-block partial of
//   scores = relu( h2 @ W_s1[:1024] + feats@W_s1[1024:] + b_s1 ) @ W_s2
// feats contribution = len*g_wf[0] + i*g_wf[1] + end*g_wf[2]  (per column).
// Deterministic: per-block partials to g_part, summed by k_final.
// ---------------------------------------------------------------------------
__global__ __launch_bounds__(256, 2)
void k_gemm3(const float* __restrict__ W_s1,
             const float* __restrict__ b_s1,
             const float* __restrict__ W_s2)
{
    __shared__ __align__(16) float sh[2304];
    float* As = sh;
    float* Bs = sh + 1024;

    int tid = threadIdx.x;
    int tx = tid % 16, ty = tid / 16;
    int m0 = blockIdx.x * 128, n0 = blockIdx.y * 128;

    int lm  = tid >> 1;          // row 0..127
    int lkh = tid & 1;           // k-offset 4*lkh
    int sA = m0 + lm; if (sA >= NSPAN) sA = NSPAN - 1;
    const float* Arow = g_h2 + (size_t)sA * HDIM;

    int br = tid >> 5;
    int bc = (tid & 31) << 2;

    float acc[8][8];
    #pragma unroll
    for (int a = 0; a < 8; ++a)
        #pragma unroll
        for (int b = 0; b < 8; ++b) acc[a][b] = 0.f;

    for (int kk = 0; kk < HDIM; kk += 8) {
        {
            const float4 av = *(const float4*)(Arow + kk + lkh * 4);
            As[(lkh * 4 + 0) * 128 + lm] = av.x;
            As[(lkh * 4 + 1) * 128 + lm] = av.y;
            As[(lkh * 4 + 2) * 128 + lm] = av.z;
            As[(lkh * 4 + 3) * 128 + lm] = av.w;
        }
        *(float4*)(Bs + br * 128 + bc) = *(const float4*)(W_s1 + (kk + br) * HDIM + n0 + bc);
        __syncthreads();

        #pragma unroll
        for (int k = 0; k < 8; ++k) {
            float a[8], b[8];
            float4 t;
            t = *(const float4*)(As + k * 128 + (ty << 2));      a[0]=t.x; a[1]=t.y; a[2]=t.z; a[3]=t.w;
            t = *(const float4*)(As + k * 128 + (ty << 2) + 64); a[4]=t.x; a[5]=t.y; a[6]=t.z; a[7]=t.w;
            t = *(const float4*)(Bs + k * 128 + (tx << 2));      b[0]=t.x; b[1]=t.y; b[2]=t.z; b[3]=t.w;
            t = *(const float4*)(Bs + k * 128 + (tx << 2) + 64); b[4]=t.x; b[5]=t.y; b[6]=t.z; b[7]=t.w;
            #pragma unroll
            for (int ii = 0; ii < 8; ++ii)
                #pragma unroll
                for (int jj = 0; jj < 8; ++jj)
                    acc[ii][jj] = fmaf(a[ii], b[jj], acc[ii][jj]);
        }
        __syncthreads();
    }

    // Per-column constants
    int cbase = n0 + (tx << 2);
    float4 t0, t1;
    float cb[8], cl[8], ci[8], ce[8], cw[8];
    t0 = *(const float4*)(b_s1 + cbase);  t1 = *(const float4*)(b_s1 + cbase + 64);
    cb[0]=t0.x;cb[1]=t0.y;cb[2]=t0.z;cb[3]=t0.w;cb[4]=t1.x;cb[5]=t1.y;cb[6]=t1.z;cb[7]=t1.w;
    t0 = *(const float4*)(g_wf + cbase);  t1 = *(const float4*)(g_wf + cbase + 64);
    cl[0]=t0.x;cl[1]=t0.y;cl[2]=t0.z;cl[3]=t0.w;cl[4]=t1.x;cl[5]=t1.y;cl[6]=t1.z;cl[7]=t1.w;
    t0 = *(const float4*)(g_wf + HDIM + cbase);  t1 = *(const float4*)(g_wf + HDIM + cbase + 64);
    ci[0]=t0.x;ci[1]=t0.y;ci[2]=t0.z;ci[3]=t0.w;ci[4]=t1.x;ci[5]=t1.y;ci[6]=t1.z;ci[7]=t1.w;
    t0 = *(const float4*)(g_wf + 2 * HDIM + cbase);  t1 = *(const float4*)(g_wf + 2 * HDIM + cbase + 64);
    ce[0]=t0.x;ce[1]=t0.y;ce[2]=t0.z;ce[3]=t0.w;ce[4]=t1.x;ce[5]=t1.y;ce[6]=t1.z;ce[7]=t1.w;
    t0 = *(const float4*)(W_s2 + cbase);  t1 = *(const float4*)(W_s2 + cbase + 64);
    cw[0]=t0.x;cw[1]=t0.y;cw[2]=t0.z;cw[3]=t0.w;cw[4]=t1.x;cw[5]=t1.y;cw[6]=t1.z;cw[7]=t1.w;

    float rs[8];
    #pragma unroll
    for (int ri = 0; ri < 8; ++ri) {
        int r = (ri < 4) ? ((ty << 2) + ri) : (64 + (ty << 2) + ri - 4);
        int gs = m0 + r; int sc = (gs < NSPAN) ? gs : (NSPAN - 1);
        int ii_ = g_si[sc], jj_ = g_sj[sc];
        float fl = (float)(jj_ - ii_ + 1);
        float fi = (float)ii_;
        float fe = (float)(jj_ + 1);
        float sum = 0.f;
        #pragma unroll
        for (int cc = 0; cc < 8; ++cc) {
            float v = acc[ri][cc] + cb[cc];
            v = fmaf(fl, cl[cc], v);
            v = fmaf(fi, ci[cc], v);
            v = fmaf(fe, ce[cc], v);
            v = fmaxf(v, 0.f);
            sum = fmaf(v, cw[cc], sum);
        }
        rs[ri] = sum;
    }

    // Cross-tx reduction in shared memory (stride 17 to avoid bank conflicts)
    #pragma unroll
    for (int ri = 0; ri < 8; ++ri) {
        int r = (ri < 4) ? ((ty << 2) + ri) : (64 + (ty << 2) + ri - 4);
        sh[r * 17 + tx] = rs[ri];
    }
    __syncthreads();
    if (tid < 128) {
        float t = 0.f;
        #pragma unroll
        for (int q = 0; q < 16; ++q) t += sh[tid * 17 + q];
        g_part[(size_t)blockIdx.y * NSPAN_PAD + m0 + tid] = t;
    }
}

// ---------------------------------------------------------------------------
// Kernel 7: final reduce over the 8 column-block partials + b_s2.
// ---------------------------------------------------------------------------
__global__ void k_final(const float* __restrict__ b_s2, float* __restrict__ out)
{
    int s = blockIdx.x * blockDim.x + threadIdx.x;
    if (s < NSPAN) {
        float t = b_s2[0];
        #pragma unroll
        for (int q = 0; q < 8; ++q) t += g_part[(size_t)q * NSPAN_PAD + s];
        out[s] = t;
    }
}

// ---------------------------------------------------------------------------
extern "C" void kernel_launch(void* const* d_in, const int* in_sizes, int n_in,
                              void* d_out, int out_size)
{
    const int*   sent    = (const int*)d_in[0];
    const int*   pos     = (const int*)d_in[1];
    const float* We_wrd  = (const float*)d_in[2];
    const float* We_pos  = (const float*)d_in[3];
    const float* W_dan1  = (const float*)d_in[4];
    const float* b_dan1  = (const float*)d_in[5];
    const float* W_dan2  = (const float*)d_in[6];
    const float* b_dan2  = (const float*)d_in[7];
    const float* W_s1    = (const float*)d_in[8];
    const float* b_s1    = (const float*)d_in[9];
    const float* W_s2    = (const float*)d_in[10];
    const float* b_s2    = (const float*)d_in[11];
    float* out = (float*)d_out;

    k_pref <<<4, 256>>>(sent, pos, We_wrd, We_pos);
    k_spans<<<N_TOK, 256>>>();
    k_wfeat<<<4, 256>>>(W_s1);
    k_gemmP<<<dim3(13, 32), 256>>>(W_dan1);
    k_gemm2<<<dim3(MTILES, 8), 256>>>(W_dan2, b_dan1, b_dan2);
    k_gemm3<<<dim3(MTILES, 8), 256>>>(W_s1, b_s1, W_s2);
    k_final<<<(NSPAN + 255) / 256, 256>>>(b_s2, out);
}

// round 3
// speedup vs baseline: 3.9852x; 3.9852x over previous
#include <cuda_runtime.h>
#include <cstdint>

// Problem constants
#define N_TOK   384
#define WDIM    512
#define EMB     1024
#define HDIM    1024
#define NSPAN   73920
#define MTILES  578
#define NSPAN_PAD (MTILES*128)

// Arch gate: tcgen05 only exists in arch-specific (sm_103a) device passes.
#if defined(__CUDA_ARCH__) && (__CUDA_ARCH__ >= 1000) && defined(__CUDA_ARCH_FEAT_SM103_ALL)
#define HAS_TCGEN05 1
#else
#define HAS_TCGEN05 0
#endif

// Scratch
__device__ float g_pref[(N_TOK + 1) * EMB];
__device__ float g_P[(N_TOK + 1) * HDIM];
__device__ float g_h2[(size_t)NSPAN * HDIM];
__device__ int   g_si[NSPAN_PAD];
__device__ int   g_sj[NSPAN_PAD];
__device__ float g_wf[3 * HDIM];
__device__ float g_part[(size_t)8 * NSPAN_PAD];
__device__ float g_Wt2[HDIM * HDIM];     // W_dan2^T  [n][k]
__device__ float g_Ws1t[HDIM * HDIM];    // W_s1[:1024]^T [n][k]

#if HAS_TCGEN05
// ---------------------------------------------------------------------------
// PTX helpers (tcgen05 path only)
// ---------------------------------------------------------------------------
__device__ __forceinline__ uint32_t smem_u32(const void* p) {
    uint32_t a;
    asm("{ .reg .u64 t; cvta.to.shared.u64 t, %1; cvt.u32.u64 %0, t; }" : "=r"(a) : "l"(p));
    return a;
}

#define MBAR_INIT(addr, cnt) \
    asm volatile("mbarrier.init.shared.b64 [%0], %1;" :: "r"(addr), "r"(cnt) : "memory")
#define MBAR_INVAL(addr) \
    asm volatile("mbarrier.inval.shared.b64 [%0];" :: "r"(addr) : "memory")

#define MBAR_WAIT_PARITY(addr, parity) do {                                        \
    uint32_t _m = (addr); uint32_t _p = (parity); uint32_t _done;                  \
    asm volatile("{\n\t.reg .pred p;\n\t"                                          \
        "mbarrier.try_wait.parity.acquire.cta.shared::cta.b64 p, [%1], %2;\n\t"    \
        "selp.b32 %0, 1, 0, p;\n\t}"                                               \
        : "=r"(_done) : "r"(_m), "r"(_p) : "memory");                              \
    if (!_done) {                                                                  \
        asm volatile("{\n\t.reg .pred P1;\n\t"                                     \
            "WL_%=:\n\t"                                                           \
            "mbarrier.try_wait.parity.acquire.cta.shared::cta.b64 P1, [%0], %1, 0x989680;\n\t" \
            "@P1 bra.uni WD_%=;\n\t"                                               \
            "bra.uni WL_%=;\n\t"                                                   \
            "WD_%=:\n\t}"                                                          \
            :: "r"(_m), "r"(_p) : "memory");                                       \
    }                                                                              \
} while (0)

#define TC_ALLOC(smem_addr, ncols) \
    asm volatile("tcgen05.alloc.cta_group::1.sync.aligned.shared::cta.b32 [%0], %1;" \
        :: "r"((uint32_t)(smem_addr)), "r"((uint32_t)(ncols)) : "memory")
#define TC_DEALLOC(tmem, ncols) \
    asm volatile("tcgen05.dealloc.cta_group::1.sync.aligned.b32 %0, %1;" \
        :: "r"(tmem), "r"((uint32_t)(ncols)))
#define TC_RELINQ() \
    asm volatile("tcgen05.relinquish_alloc_permit.cta_group::1.sync.aligned;")
#define TC_COMMIT(mbar) \
    asm volatile("tcgen05.commit.cta_group::1.mbarrier::arrive::one.shared::cluster.b64 [%0];" \
        :: "r"((uint32_t)(mbar)) : "memory")
#define TC_FENCE_AFTER()  asm volatile("tcgen05.fence::after_thread_sync;" ::: "memory")
#define TC_WAIT_LD()      asm volatile("tcgen05.wait::ld.sync.aligned;" ::: "memory")
#define FENCE_ASYNC_SHARED() asm volatile("fence.proxy.async.shared::cta;" ::: "memory")

#define TC_LD_X32(r, tmem_addr) \
    asm volatile("tcgen05.ld.sync.aligned.32x32b.x32.b32 " \
        "{%0, %1, %2, %3, %4, %5, %6, %7, %8, %9, %10, %11, %12, %13, %14, %15, " \
        " %16, %17, %18, %19, %20, %21, %22, %23, %24, %25, %26, %27, %28, %29, %30, %31}, [%32];" \
        : "=r"((r)[0]),  "=r"((r)[1]),  "=r"((r)[2]),  "=r"((r)[3]), \
          "=r"((r)[4]),  "=r"((r)[5]),  "=r"((r)[6]),  "=r"((r)[7]), \
          "=r"((r)[8]),  "=r"((r)[9]),  "=r"((r)[10]), "=r"((r)[11]), \
          "=r"((r)[12]), "=r"((r)[13]), "=r"((r)[14]), "=r"((r)[15]), \
          "=r"((r)[16]), "=r"((r)[17]), "=r"((r)[18]), "=r"((r)[19]), \
          "=r"((r)[20]), "=r"((r)[21]), "=r"((r)[22]), "=r"((r)[23]), \
          "=r"((r)[24]), "=r"((r)[25]), "=r"((r)[26]), "=r"((r)[27]), \
          "=r"((r)[28]), "=r"((r)[29]), "=r"((r)[30]), "=r"((r)[31]) \
        : "r"(tmem_addr))

// SW128 K-major SMEM descriptor (LBO=1, SBO=64, version=1, layout=2)
static constexpr uint64_t DESC_BASE_SW128 =
    (uint64_t(2) << 61) | (uint64_t(1) << 46) | (uint64_t(64) << 32) | (uint64_t(1) << 16);
__device__ __forceinline__ uint64_t make_desc(uint32_t addr) {
    return DESC_BASE_SW128 | ((uint64_t)(addr >> 4) & 0x3FFF);
}

__device__ __forceinline__ void mma_tf32_ss(uint32_t d, uint64_t ad, uint64_t bd,
                                            uint32_t idesc, bool acc) {
    uint32_t en = acc ? 1u : 0u;
    asm volatile(
        "{\n\t.reg .pred p;\n\t"
        "setp.ne.u32 p, %4, 0;\n\t"
        "tcgen05.mma.cta_group::1.kind::tf32 [%0], %1, %2, %3, {%5, %5, %5, %5}, p;\n\t"
        "}"
        :: "r"(d), "l"(ad), "l"(bd), "r"(idesc), "r"(en), "r"(0u)
        : "memory");
}
// idesc: dtype=F32(1<<4), a=TF32(2<<7), b=TF32(2<<10), N=128(16<<17), M=128(8<<24)
#define IDESC_TF32 ((1u<<4)|(2u<<7)|(2u<<10)|(16u<<17)|(8u<<24))
#endif  // HAS_TCGEN05

// ---------------------------------------------------------------------------
// Kernel: embedding prefix sums
// ---------------------------------------------------------------------------
__global__ void k_pref(const int* __restrict__ sent, const int* __restrict__ pos,
                       const float* __restrict__ We_wrd, const float* __restrict__ We_pos)
{
    int c = blockIdx.x * blockDim.x + threadIdx.x;
    if (c >= EMB) return;
    bool isPos = (c < WDIM);
    const float* base = isPos ? (We_pos + c) : (We_wrd + (c - WDIM));
    const int*   idx  = isPos ? pos : sent;
    float run = 0.f;
    g_pref[c] = 0.f;
    #pragma unroll 4
    for (int t = 0; t < N_TOK; ++t) {
        run += base[(size_t)idx[t] * WDIM];
        g_pref[(t + 1) * EMB + c] = run;
    }
}

// ---------------------------------------------------------------------------
// Kernel: span tables
// ---------------------------------------------------------------------------
__global__ void k_spans()
{
    int i = blockIdx.x;
    int base = i * N_TOK - (i * (i - 1)) / 2;
    for (int j = i + threadIdx.x; j < N_TOK; j += blockDim.x) {
        int s = base + (j - i);
        g_si[s] = i;
        g_sj[s] = j;
    }
    if (blockIdx.x == 0) {
        for (int s = NSPAN + threadIdx.x; s < NSPAN_PAD; s += blockDim.x) {
            g_si[s] = 0; g_sj[s] = 0;
        }
    }
}

// ---------------------------------------------------------------------------
// Kernel: feat weight folding
// ---------------------------------------------------------------------------
__global__ void k_wfeat(const float* __restrict__ W_s1)
{
    int n = blockIdx.x * blockDim.x + threadIdx.x;
    if (n >= HDIM) return;
    float sl = 0.f, si = 0.f, se = 0.f;
    #pragma unroll
    for (int r = 0; r < 16; ++r) {
        sl += W_s1[(HDIM +      r) * HDIM + n];
        si += W_s1[(HDIM + 16 + r) * HDIM + n];
        se += W_s1[(HDIM + 32 + r) * HDIM + n];
    }
    g_wf[n] = sl; g_wf[HDIM + n] = si; g_wf[2 * HDIM + n] = se;
}

// ---------------------------------------------------------------------------
// Kernel: 1024x1024 transpose
// ---------------------------------------------------------------------------
__global__ void k_transp(const float* __restrict__ src, float* __restrict__ dst)
{
    __shared__ float t[32][33];
    int x = blockIdx.x * 32 + threadIdx.x;
    int y = blockIdx.y * 32 + threadIdx.y;
    #pragma unroll
    for (int j = 0; j < 32; j += 8)
        t[threadIdx.y + j][threadIdx.x] = src[(size_t)(y + j) * HDIM + x];
    __syncthreads();
    x = blockIdx.y * 32 + threadIdx.x;
    y = blockIdx.x * 32 + threadIdx.y;
    #pragma unroll
    for (int j = 0; j < 32; j += 8)
        dst[(size_t)(y + j) * HDIM + x] = t[threadIdx.x][threadIdx.y + j];
}

// ---------------------------------------------------------------------------
// Kernel: P = pref @ W_dan1  (64x64 tiles, 4x4/thread)
// ---------------------------------------------------------------------------
__global__ __launch_bounds__(256) void k_gemmP(const float* __restrict__ W)
{
    __shared__ float As[64][17];
    __shared__ float Bs[16][68];
    int tid = threadIdx.x;
    int tx = tid % 16, ty = tid / 16;
    int m0 = blockIdx.x * 64, n0 = blockIdx.y * 64;
    float acc[4][4] = {};

    for (int kk = 0; kk < EMB; kk += 16) {
        #pragma unroll
        for (int e = tid; e < 64 * 16; e += 256) {
            int r = e >> 4, c = e & 15;
            int gm = m0 + r;
            As[r][c] = (gm <= N_TOK) ? g_pref[gm * EMB + kk + c] : 0.f;
        }
        #pragma unroll
        for (int e = tid; e < 16 * 64; e += 256) {
            int r = e >> 6, c = e & 63;
            Bs[r][c] = W[(kk + r) * HDIM + n0 + c];
        }
        __syncthreads();
        #pragma unroll
        for (int k = 0; k < 16; ++k) {
            float a[4], b[4];
            #pragma unroll
            for (int q = 0; q < 4; ++q) { a[q] = As[ty * 4 + q][k]; b[q] = Bs[k][tx * 4 + q]; }
            #pragma unroll
            for (int i = 0; i < 4; ++i)
                #pragma unroll
                for (int j = 0; j < 4; ++j)
                    acc[i][j] = fmaf(a[i], b[j], acc[i][j]);
        }
        __syncthreads();
    }
    #pragma unroll
    for (int i = 0; i < 4; ++i) {
        int gm = m0 + ty * 4 + i;
        if (gm <= N_TOK)
            #pragma unroll
            for (int j = 0; j < 4; ++j)
                g_P[gm * HDIM + n0 + tx * 4 + j] = acc[i][j];
    }
}

// ---------------------------------------------------------------------------
// Big GEMM, 128x128 tile, K=1024.
// MODE 2: A = h1 fused from P; epilogue relu(+b2) -> g_h2
// MODE 3: A = g_h2; epilogue bias+feats+relu, dot W_s2 -> g_part
// tcgen05 tf32 path when available; SIMT fp32 fallback otherwise.
//   W  = original [K,N] weight (fallback), Bt = transposed [N,K] (tensor path)
// ---------------------------------------------------------------------------
template <int MODE>
__global__
#if HAS_TCGEN05
__launch_bounds__(256, 4)
#else
__launch_bounds__(256, 2)
#endif
void k_gemm_big(const float* __restrict__ W,
                const float* __restrict__ Bt,
                const float* __restrict__ bias1,   // b_dan1 (MODE 2)
                const float* __restrict__ bias2,   // b_dan2 / b_s1
                const float* __restrict__ Ws2)     // MODE 3
{
#if HAS_TCGEN05
    // ======================= tcgen05 tf32 path =======================
    __shared__ __align__(16) float sA[128 * 32];
    __shared__ __align__(16) float sB[128 * 32];
    __shared__ float sepi[5 * 128];
    __shared__ int   s_x[128];
    __shared__ int   s_y[128];
    __shared__ float s_inv[128];
    __shared__ __align__(8) unsigned long long s_mbar;
    __shared__ uint32_t s_tmemptr;

    const int tid = threadIdx.x;
    const int m0 = blockIdx.x * 128, n0 = blockIdx.y * 128;

    if (tid < 32) {
        TC_ALLOC(smem_u32(&s_tmemptr), 128);
        TC_RELINQ();
    }
    if (tid == 0) MBAR_INIT(smem_u32(&s_mbar), 1);

    if (MODE == 2) {
        if (tid < 128) sepi[tid] = bias2[n0 + tid];
    } else {
        for (int e = tid; e < 128; e += 256) {
            sepi[e]       = bias2[n0 + e];
            sepi[128 + e] = g_wf[n0 + e];
            sepi[256 + e] = g_wf[HDIM + n0 + e];
            sepi[384 + e] = g_wf[2 * HDIM + n0 + e];
            sepi[512 + e] = Ws2[n0 + e];
        }
    }
    if (tid < 128) {
        int s = m0 + tid; if (s >= NSPAN) s = NSPAN - 1;
        if (MODE == 2) {
            int i_ = g_si[s], j_ = g_sj[s];
            s_x[tid] = j_ + 1; s_y[tid] = i_;
            s_inv[tid] = 1.0f / (float)(j_ - i_ + 1);
        } else {
            s_x[tid] = s;
        }
    }
    __syncthreads();
    const uint32_t tmem = s_tmemptr;
    const uint32_t mbarA = smem_u32(&s_mbar);
    const uint64_t adesc = make_desc(smem_u32(sA));
    const uint64_t bdesc = make_desc(smem_u32(sB));

    int ph = 0;
    #pragma unroll 1
    for (int c = 0; c < 32; ++c) {
        if (c > 0) { MBAR_WAIT_PARITY(mbarA, ph); ph ^= 1; }
        const int kk = c * 32;
        #pragma unroll
        for (int u = 0; u < 4; ++u) {
            int idx = tid + u * 256;
            int r = idx >> 3;
            int kc = (idx & 7) * 4;
            int byte = r * 128 + kc * 4;
            int sw = byte ^ ((byte >> 3) & 0x70);
            float4 v;
            if (MODE == 2) {
                const float4 e4 = *(const float4*)(g_P + (size_t)s_x[r] * HDIM + kk + kc);
                const float4 i4 = *(const float4*)(g_P + (size_t)s_y[r] * HDIM + kk + kc);
                const float4 b4 = *(const float4*)(bias1 + kk + kc);
                float inv = s_inv[r];
                v.x = fmaxf(fmaf(e4.x - i4.x, inv, b4.x), 0.f);
                v.y = fmaxf(fmaf(e4.y - i4.y, inv, b4.y), 0.f);
                v.z = fmaxf(fmaf(e4.z - i4.z, inv, b4.z), 0.f);
                v.w = fmaxf(fmaf(e4.w - i4.w, inv, b4.w), 0.f);
            } else {
                v = *(const float4*)(g_h2 + (size_t)s_x[r] * HDIM + kk + kc);
            }
            *(float4*)((char*)sA + sw) = v;
            float4 w = *(const float4*)(Bt + (size_t)(n0 + r) * HDIM + kk + kc);
            *(float4*)((char*)sB + sw) = w;
        }
        __syncthreads();
        if (tid == 0) {
            FENCE_ASYNC_SHARED();
            #pragma unroll
            for (int st = 0; st < 4; ++st)
                mma_tf32_ss(tmem, adesc + st * 2, bdesc + st * 2, IDESC_TF32,
                            (c > 0) || (st > 0));
            TC_COMMIT(mbarA);
        }
    }
    MBAR_WAIT_PARITY(mbarA, ph);
    TC_FENCE_AFTER();

    if (tid < 128) {
        if (MODE == 2) {
            int gs = m0 + tid;
            bool ok = gs < NSPAN;
            float* orow = g_h2 + (size_t)(ok ? gs : 0) * HDIM + n0;
            #pragma unroll 1
            for (int nb = 0; nb < 4; ++nb) {
                uint32_t r[32];
                TC_LD_X32(r, tmem + nb * 32);
                TC_WAIT_LD();
                if (ok) {
                    #pragma unroll
                    for (int q = 0; q < 32; q += 4) {
                        float4 o;
                        o.x = fmaxf(__uint_as_float(r[q + 0]) + sepi[nb * 32 + q + 0], 0.f);
                        o.y = fmaxf(__uint_as_float(r[q + 1]) + sepi[nb * 32 + q + 1], 0.f);
                        o.z = fmaxf(__uint_as_float(r[q + 2]) + sepi[nb * 32 + q + 2], 0.f);
                        o.w = fmaxf(__uint_as_float(r[q + 3]) + sepi[nb * 32 + q + 3], 0.f);
                        *(float4*)(orow + nb * 32 + q) = o;
                    }
                }
            }
        } else {
            int gs = m0 + tid;
            int sc = (gs < NSPAN) ? gs : (NSPAN - 1);
            int i_ = g_si[sc], j_ = g_sj[sc];
            float fl = (float)(j_ - i_ + 1);
            float fi = (float)i_;
            float fe = (float)(j_ + 1);
            float sum = 0.f;
            #pragma unroll 1
            for (int nb = 0; nb < 4; ++nb) {
                uint32_t r[32];
                TC_LD_X32(r, tmem + nb * 32);
                TC_WAIT_LD();
                #pragma unroll
                for (int q = 0; q < 32; ++q) {
                    int n = nb * 32 + q;
                    float v = __uint_as_float(r[q]) + sepi[n];
                    v = fmaf(fl, sepi[128 + n], v);
                    v = fmaf(fi, sepi[256 + n], v);
                    v = fmaf(fe, sepi[384 + n], v);
                    v = fmaxf(v, 0.f);
                    sum = fmaf(v, sepi[512 + n], sum);
                }
            }
            g_part[(size_t)blockIdx.y * NSPAN_PAD + m0 + tid] = sum;
        }
    }
    __syncthreads();
    if (tid == 0) MBAR_INVAL(mbarA);
    __syncthreads();
    if (tid < 32) TC_DEALLOC(tmem, 128);

#else
    // ======================= SIMT fp32 fallback =======================
    __shared__ __align__(16) float sh[2304];
    float* As = sh;
    float* Bs = sh + 1024;

    int tid = threadIdx.x;
    int tx = tid % 16, ty = tid / 16;
    int m0 = blockIdx.x * 128, n0 = blockIdx.y * 128;

    // A-producer assignment
    int lm, lkh;
    int xe = 0, yi = 0;          // MODE2: end/start rows
    float invlen = 0.f;
    const float* Arow = nullptr; // MODE3
    if (MODE == 2) {
        lm = tid & 127; lkh = tid >> 7;
        int s = m0 + lm; if (s >= NSPAN) s = NSPAN - 1;
        int i_ = g_si[s], j_ = g_sj[s];
        invlen = 1.0f / (float)(j_ - i_ + 1);
        xe = j_ + 1; yi = i_;
    } else {
        lm = tid >> 1; lkh = tid & 1;
        int sA_ = m0 + lm; if (sA_ >= NSPAN) sA_ = NSPAN - 1;
        Arow = g_h2 + (size_t)sA_ * HDIM;
    }

    int br = tid >> 5;
    int bc = (tid & 31) << 2;

    float acc[8][8];
    #pragma unroll
    for (int a = 0; a < 8; ++a)
        #pragma unroll
        for (int b = 0; b < 8; ++b) acc[a][b] = 0.f;

    for (int kk = 0; kk < HDIM; kk += 8) {
        if (MODE == 2) {
            const float4 pe = *(const float4*)(g_P + (size_t)xe * HDIM + kk + lkh * 4);
            const float4 pi = *(const float4*)(g_P + (size_t)yi * HDIM + kk + lkh * 4);
            const float4 bb = *(const float4*)(bias1 + kk + lkh * 4);
            As[(lkh * 4 + 0) * 128 + lm] = fmaxf(fmaf(pe.x - pi.x, invlen, bb.x), 0.f);
            As[(lkh * 4 + 1) * 128 + lm] = fmaxf(fmaf(pe.y - pi.y, invlen, bb.y), 0.f);
            As[(lkh * 4 + 2) * 128 + lm] = fmaxf(fmaf(pe.z - pi.z, invlen, bb.z), 0.f);
            As[(lkh * 4 + 3) * 128 + lm] = fmaxf(fmaf(pe.w - pi.w, invlen, bb.w), 0.f);
        } else {
            const float4 av = *(const float4*)(Arow + kk + lkh * 4);
            As[(lkh * 4 + 0) * 128 + lm] = av.x;
            As[(lkh * 4 + 1) * 128 + lm] = av.y;
            As[(lkh * 4 + 2) * 128 + lm] = av.z;
            As[(lkh * 4 + 3) * 128 + lm] = av.w;
        }
        *(float4*)(Bs + br * 128 + bc) = *(const float4*)(W + (size_t)(kk + br) * HDIM + n0 + bc);
        __syncthreads();

        #pragma unroll
        for (int k = 0; k < 8; ++k) {
            float a[8], b[8];
            float4 t;
            t = *(const float4*)(As + k * 128 + (ty << 2));      a[0]=t.x; a[1]=t.y; a[2]=t.z; a[3]=t.w;
            t = *(const float4*)(As + k * 128 + (ty << 2) + 64); a[4]=t.x; a[5]=t.y; a[6]=t.z; a[7]=t.w;
            t = *(const float4*)(Bs + k * 128 + (tx << 2));      b[0]=t.x; b[1]=t.y; b[2]=t.z; b[3]=t.w;
            t = *(const float4*)(Bs + k * 128 + (tx << 2) + 64); b[4]=t.x; b[5]=t.y; b[6]=t.z; b[7]=t.w;
            #pragma unroll
            for (int ii = 0; ii < 8; ++ii)
                #pragma unroll
                for (int jj = 0; jj < 8; ++jj)
                    acc[ii][jj] = fmaf(a[ii], b[jj], acc[ii][jj]);
        }
        __syncthreads();
    }

    if (MODE == 2) {
        float4 bn0 = *(const float4*)(bias2 + n0 + (tx << 2));
        float4 bn1 = *(const float4*)(bias2 + n0 + (tx << 2) + 64);
        float cb[8] = {bn0.x, bn0.y, bn0.z, bn0.w, bn1.x, bn1.y, bn1.z, bn1.w};
        #pragma unroll
        for (int ri = 0; ri < 8; ++ri) {
            int r = (ri < 4) ? ((ty << 2) + ri) : (64 + (ty << 2) + ri - 4);
            int gs = m0 + r;
            if (gs < NSPAN) {
                float4 o0, o1;
                o0.x = fmaxf(acc[ri][0] + cb[0], 0.f);
                o0.y = fmaxf(acc[ri][1] + cb[1], 0.f);
                o0.z = fmaxf(acc[ri][2] + cb[2], 0.f);
                o0.w = fmaxf(acc[ri][3] + cb[3], 0.f);
                o1.x = fmaxf(acc[ri][4] + cb[4], 0.f);
                o1.y = fmaxf(acc[ri][5] + cb[5], 0.f);
                o1.z = fmaxf(acc[ri][6] + cb[6], 0.f);
                o1.w = fmaxf(acc[ri][7] + cb[7], 0.f);
                *(float4*)(g_h2 + (size_t)gs * HDIM + n0 + (tx << 2))      = o0;
                *(float4*)(g_h2 + (size_t)gs * HDIM + n0 + (tx << 2) + 64) = o1;
            }
        }
    } else {
        int cbase = n0 + (tx << 2);
        float4 t0, t1;
        float cb[8], cl[8], ci[8], ce[8], cw[8];
        t0 = *(const float4*)(bias2 + cbase);  t1 = *(const float4*)(bias2 + cbase + 64);
        cb[0]=t0.x;cb[1]=t0.y;cb[2]=t0.z;cb[3]=t0.w;cb[4]=t1.x;cb[5]=t1.y;cb[6]=t1.z;cb[7]=t1.w;
        t0 = *(const float4*)(g_wf + cbase);  t1 = *(const float4*)(g_wf + cbase + 64);
        cl[0]=t0.x;cl[1]=t0.y;cl[2]=t0.z;cl[3]=t0.w;cl[4]=t1.x;cl[5]=t1.y;cl[6]=t1.z;cl[7]=t1.w;
        t0 = *(const float4*)(g_wf + HDIM + cbase);  t1 = *(const float4*)(g_wf + HDIM + cbase + 64);
        ci[0]=t0.x;ci[1]=t0.y;ci[2]=t0.z;ci[3]=t0.w;ci[4]=t1.x;ci[5]=t1.y;ci[6]=t1.z;ci[7]=t1.w;
        t0 = *(const float4*)(g_wf + 2 * HDIM + cbase);  t1 = *(const float4*)(g_wf + 2 * HDIM + cbase + 64);
        ce[0]=t0.x;ce[1]=t0.y;ce[2]=t0.z;ce[3]=t0.w;ce[4]=t1.x;ce[5]=t1.y;ce[6]=t1.z;ce[7]=t1.w;
        t0 = *(const float4*)(Ws2 + cbase);  t1 = *(const float4*)(Ws2 + cbase + 64);
        cw[0]=t0.x;cw[1]=t0.y;cw[2]=t0.z;cw[3]=t0.w;cw[4]=t1.x;cw[5]=t1.y;cw[6]=t1.z;cw[7]=t1.w;

        float rs[8];
        #pragma unroll
        for (int ri = 0; ri < 8; ++ri) {
            int r = (ri < 4) ? ((ty << 2) + ri) : (64 + (ty << 2) + ri - 4);
            int gs = m0 + r; int sc = (gs < NSPAN) ? gs : (NSPAN - 1);
            int ii_ = g_si[sc], jj_ = g_sj[sc];
            float fl = (float)(jj_ - ii_ + 1);
            float fi = (float)ii_;
            float fe = (float)(jj_ + 1);
            float sum = 0.f;
            #pragma unroll
            for (int cc = 0; cc < 8; ++cc) {
                float v = acc[ri][cc] + cb[cc];
                v = fmaf(fl, cl[cc], v);
                v = fmaf(fi, ci[cc], v);
                v = fmaf(fe, ce[cc], v);
                v = fmaxf(v, 0.f);
                sum = fmaf(v, cw[cc], sum);
            }
            rs[ri] = sum;
        }
        #pragma unroll
        for (int ri = 0; ri < 8; ++ri) {
            int r = (ri < 4) ? ((ty << 2) + ri) : (64 + (ty << 2) + ri - 4);
            sh[r * 17 + tx] = rs[ri];
        }
        __syncthreads();
        if (tid < 128) {
            float t = 0.f;
            #pragma unroll
            for (int q = 0; q < 16; ++q) t += sh[tid * 17 + q];
            g_part[(size_t)blockIdx.y * NSPAN_PAD + m0 + tid] = t;
        }
    }
#endif
}

// ---------------------------------------------------------------------------
// Final reduce
// ---------------------------------------------------------------------------
__global__ void k_final(const float* __restrict__ b_s2, float* __restrict__ out)
{
    int s = blockIdx.x * blockDim.x + threadIdx.x;
    if (s < NSPAN) {
        float t = b_s2[0];
        #pragma unroll
        for (int q = 0; q < 8; ++q) t += g_part[(size_t)q * NSPAN_PAD + s];
        out[s] = t;
    }
}

// ---------------------------------------------------------------------------
extern "C" void kernel_launch(void* const* d_in, const int* in_sizes, int n_in,
                              void* d_out, int out_size)
{
    const int*   sent    = (const int*)d_in[0];
    const int*   pos     = (const int*)d_in[1];
    const float* We_wrd  = (const float*)d_in[2];
    const float* We_pos  = (const float*)d_in[3];
    const float* W_dan1  = (const float*)d_in[4];
    const float* b_dan1  = (const float*)d_in[5];
    const float* W_dan2  = (const float*)d_in[6];
    const float* b_dan2  = (const float*)d_in[7];
    const float* W_s1    = (const float*)d_in[8];
    const float* b_s1    = (const float*)d_in[9];
    const float* W_s2    = (const float*)d_in[10];
    const float* b_s2    = (const float*)d_in[11];
    float* out = (float*)d_out;

    float* wt2;  cudaGetSymbolAddress((void**)&wt2,  g_Wt2);
    float* ws1t; cudaGetSymbolAddress((void**)&ws1t, g_Ws1t);

    k_pref <<<4, 256>>>(sent, pos, We_wrd, We_pos);
    k_spans<<<N_TOK, 256>>>();
    k_wfeat<<<4, 256>>>(W_s1);
    k_transp<<<dim3(32, 32), dim3(32, 8)>>>(W_dan2, wt2);
    k_transp<<<dim3(32, 32), dim3(32, 8)>>>(W_s1, ws1t);
    k_gemmP<<<dim3(7, 16), 256>>>(W_dan1);
    k_gemm_big<2><<<dim3(MTILES, 8), 256>>>(W_dan2, wt2,  b_dan1, b_dan2, nullptr);
    k_gemm_big<3><<<dim3(MTILES, 8), 256>>>(W_s1,   ws1t, nullptr, b_s1,  W_s2);
    k_final<<<(NSPAN + 255) / 256, 256>>>(b_s2, out);
}

// round 4
// speedup vs baseline: 6.1286x; 1.5379x over previous
#include <cuda_runtime.h>
#include <cuda_bf16.h>
#include <cstdint>

// Problem constants
#define N_TOK   384
#define WDIM    512
#define EMB     1024
#define HDIM    1024
#define NSPAN   73920
#define MTILES  578
#define NSPAN_PAD (MTILES*128)

// Arch gate: tcgen05 only exists in arch-specific (sm_103a) device passes.
#if defined(__CUDA_ARCH__) && (__CUDA_ARCH__ >= 1000) && defined(__CUDA_ARCH_FEAT_SM103_ALL)
#define HAS_TCGEN05 1
#else
#define HAS_TCGEN05 0
#endif

// Scratch
__device__ float g_pref[(N_TOK + 1) * EMB];
__device__ float g_P[(N_TOK + 1) * HDIM];
__device__ __nv_bfloat16 g_h2b[(size_t)NSPAN * HDIM];   // DAN layer-2 output, bf16 (151MB)
__device__ int   g_si[NSPAN_PAD];
__device__ int   g_sj[NSPAN_PAD];
__device__ float g_wf[3 * HDIM];
__device__ float g_part[(size_t)8 * NSPAN_PAD];
__device__ __nv_bfloat16 g_Wt2b[HDIM * HDIM];    // W_dan2^T  [n][k] bf16
__device__ __nv_bfloat16 g_Ws1tb[HDIM * HDIM];   // W_s1[:1024]^T [n][k] bf16

__device__ __forceinline__ uint32_t pack_bf16(float a, float b) {
    __nv_bfloat162 h = __floats2bfloat162_rn(a, b);
    return *reinterpret_cast<uint32_t*>(&h);
}

#if HAS_TCGEN05
// ---------------------------------------------------------------------------
// PTX helpers (tcgen05 path only)
// ---------------------------------------------------------------------------
__device__ __forceinline__ uint32_t smem_u32(const void* p) {
    uint32_t a;
    asm("{ .reg .u64 t; cvta.to.shared.u64 t, %1; cvt.u32.u64 %0, t; }" : "=r"(a) : "l"(p));
    return a;
}

#define MBAR_INIT(addr, cnt) \
    asm volatile("mbarrier.init.shared.b64 [%0], %1;" :: "r"(addr), "r"(cnt) : "memory")
#define MBAR_INVAL(addr) \
    asm volatile("mbarrier.inval.shared.b64 [%0];" :: "r"(addr) : "memory")

#define MBAR_WAIT_PARITY(addr, parity) do {                                        \
    uint32_t _m = (addr); uint32_t _p = (parity); uint32_t _done;                  \
    asm volatile("{\n\t.reg .pred p;\n\t"                                          \
        "mbarrier.try_wait.parity.acquire.cta.shared::cta.b64 p, [%1], %2;\n\t"    \
        "selp.b32 %0, 1, 0, p;\n\t}"                                               \
        : "=r"(_done) : "r"(_m), "r"(_p) : "memory");                              \
    if (!_done) {                                                                  \
        asm volatile("{\n\t.reg .pred P1;\n\t"                                     \
            "WL_%=:\n\t"                                                           \
            "mbarrier.try_wait.parity.acquire.cta.shared::cta.b64 P1, [%0], %1, 0x989680;\n\t" \
            "@P1 bra.uni WD_%=;\n\t"                                               \
            "bra.uni WL_%=;\n\t"                                                   \
            "WD_%=:\n\t}"                                                          \
            :: "r"(_m), "r"(_p) : "memory");                                       \
    }                                                                              \
} while (0)

#define TC_ALLOC(smem_addr, ncols) \
    asm volatile("tcgen05.alloc.cta_group::1.sync.aligned.shared::cta.b32 [%0], %1;" \
        :: "r"((uint32_t)(smem_addr)), "r"((uint32_t)(ncols)) : "memory")
#define TC_DEALLOC(tmem, ncols) \
    asm volatile("tcgen05.dealloc.cta_group::1.sync.aligned.b32 %0, %1;" \
        :: "r"(tmem), "r"((uint32_t)(ncols)))
#define TC_RELINQ() \
    asm volatile("tcgen05.relinquish_alloc_permit.cta_group::1.sync.aligned;")
#define TC_COMMIT(mbar) \
    asm volatile("tcgen05.commit.cta_group::1.mbarrier::arrive::one.shared::cluster.b64 [%0];" \
        :: "r"((uint32_t)(mbar)) : "memory")
#define TC_FENCE_AFTER()  asm volatile("tcgen05.fence::after_thread_sync;" ::: "memory")
#define TC_WAIT_LD()      asm volatile("tcgen05.wait::ld.sync.aligned;" ::: "memory")
#define FENCE_ASYNC_SHARED() asm volatile("fence.proxy.async.shared::cta;" ::: "memory")

#define TC_LD_X32(r, tmem_addr) \
    asm volatile("tcgen05.ld.sync.aligned.32x32b.x32.b32 " \
        "{%0, %1, %2, %3, %4, %5, %6, %7, %8, %9, %10, %11, %12, %13, %14, %15, " \
        " %16, %17, %18, %19, %20, %21, %22, %23, %24, %25, %26, %27, %28, %29, %30, %31}, [%32];" \
        : "=r"((r)[0]),  "=r"((r)[1]),  "=r"((r)[2]),  "=r"((r)[3]), \
          "=r"((r)[4]),  "=r"((r)[5]),  "=r"((r)[6]),  "=r"((r)[7]), \
          "=r"((r)[8]),  "=r"((r)[9]),  "=r"((r)[10]), "=r"((r)[11]), \
          "=r"((r)[12]), "=r"((r)[13]), "=r"((r)[14]), "=r"((r)[15]), \
          "=r"((r)[16]), "=r"((r)[17]), "=r"((r)[18]), "=r"((r)[19]), \
          "=r"((r)[20]), "=r"((r)[21]), "=r"((r)[22]), "=r"((r)[23]), \
          "=r"((r)[24]), "=r"((r)[25]), "=r"((r)[26]), "=r"((r)[27]), \
          "=r"((r)[28]), "=r"((r)[29]), "=r"((r)[30]), "=r"((r)[31]) \
        : "r"(tmem_addr))

// SW128 K-major SMEM descriptor (LBO=1, SBO=64, version=1, layout=2)
static constexpr uint64_t DESC_BASE_SW128 =
    (uint64_t(2) << 61) | (uint64_t(1) << 46) | (uint64_t(64) << 32) | (uint64_t(1) << 16);
__device__ __forceinline__ uint64_t make_desc(uint32_t addr) {
    return DESC_BASE_SW128 | ((uint64_t)(addr >> 4) & 0x3FFF);
}

// bf16 SS MMA, cta_group::1, fp32 accum
__device__ __forceinline__ void mma_bf16_ss(uint32_t d, uint64_t ad, uint64_t bd,
                                            uint32_t idesc, bool acc) {
    uint32_t en = acc ? 1u : 0u;
    asm volatile(
        "{\n\t.reg .pred p;\n\t"
        "setp.ne.u32 p, %4, 0;\n\t"
        "tcgen05.mma.cta_group::1.kind::f16 [%0], %1, %2, %3, {%5, %5, %5, %5}, p;\n\t"
        "}"
        :: "r"(d), "l"(ad), "l"(bd), "r"(idesc), "r"(en), "r"(0u)
        : "memory");
}
// idesc: dtype=F32(1<<4), a=BF16(1<<7), b=BF16(1<<10), N=128(16<<17), M=128(8<<24)
#define IDESC_BF16 ((1u<<4)|(1u<<7)|(1u<<10)|(16u<<17)|(8u<<24))
#endif  // HAS_TCGEN05

// ---------------------------------------------------------------------------
// Kernel: embedding prefix sums
// ---------------------------------------------------------------------------
__global__ void k_pref(const int* __restrict__ sent, const int* __restrict__ pos,
                       const float* __restrict__ We_wrd, const float* __restrict__ We_pos)
{
    int c = blockIdx.x * blockDim.x + threadIdx.x;
    if (c >= EMB) return;
    bool isPos = (c < WDIM);
    const float* base = isPos ? (We_pos + c) : (We_wrd + (c - WDIM));
    const int*   idx  = isPos ? pos : sent;
    float run = 0.f;
    g_pref[c] = 0.f;
    #pragma unroll 4
    for (int t = 0; t < N_TOK; ++t) {
        run += base[(size_t)idx[t] * WDIM];
        g_pref[(t + 1) * EMB + c] = run;
    }
}

// ---------------------------------------------------------------------------
// Kernel: span tables
// ---------------------------------------------------------------------------
__global__ void k_spans()
{
    int i = blockIdx.x;
    int base = i * N_TOK - (i * (i - 1)) / 2;
    for (int j = i + threadIdx.x; j < N_TOK; j += blockDim.x) {
        int s = base + (j - i);
        g_si[s] = i;
        g_sj[s] = j;
    }
    if (blockIdx.x == 0) {
        for (int s = NSPAN + threadIdx.x; s < NSPAN_PAD; s += blockDim.x) {
            g_si[s] = 0; g_sj[s] = 0;
        }
    }
}

// ---------------------------------------------------------------------------
// Kernel: feat weight folding
// ---------------------------------------------------------------------------
__global__ void k_wfeat(const float* __restrict__ W_s1)
{
    int n = blockIdx.x * blockDim.x + threadIdx.x;
    if (n >= HDIM) return;
    float sl = 0.f, si = 0.f, se = 0.f;
    #pragma unroll
    for (int r = 0; r < 16; ++r) {
        sl += W_s1[(HDIM +      r) * HDIM + n];
        si += W_s1[(HDIM + 16 + r) * HDIM + n];
        se += W_s1[(HDIM + 32 + r) * HDIM + n];
    }
    g_wf[n] = sl; g_wf[HDIM + n] = si; g_wf[2 * HDIM + n] = se;
}

// ---------------------------------------------------------------------------
// Kernel: 1024x1024 transpose + fp32->bf16 convert
// ---------------------------------------------------------------------------
__global__ void k_transp(const float* __restrict__ src, __nv_bfloat16* __restrict__ dst)
{
    __shared__ float t[32][33];
    int x = blockIdx.x * 32 + threadIdx.x;
    int y = blockIdx.y * 32 + threadIdx.y;
    #pragma unroll
    for (int j = 0; j < 32; j += 8)
        t[threadIdx.y + j][threadIdx.x] = src[(size_t)(y + j) * HDIM + x];
    __syncthreads();
    x = blockIdx.y * 32 + threadIdx.x;
    y = blockIdx.x * 32 + threadIdx.y;
    #pragma unroll
    for (int j = 0; j < 32; j += 8)
        dst[(size_t)(y + j) * HDIM + x] = __float2bfloat16(t[threadIdx.x][threadIdx.y + j]);
}

// ---------------------------------------------------------------------------
// Kernel: P = pref @ W_dan1  (64x64 tiles, 4x4/thread) fp32
// ---------------------------------------------------------------------------
__global__ __launch_bounds__(256) void k_gemmP(const float* __restrict__ W)
{
    __shared__ float As[64][17];
    __shared__ float Bs[16][68];
    int tid = threadIdx.x;
    int tx = tid % 16, ty = tid / 16;
    int m0 = blockIdx.x * 64, n0 = blockIdx.y * 64;
    float acc[4][4] = {};

    for (int kk = 0; kk < EMB; kk += 16) {
        #pragma unroll
        for (int e = tid; e < 64 * 16; e += 256) {
            int r = e >> 4, c = e & 15;
            int gm = m0 + r;
            As[r][c] = (gm <= N_TOK) ? g_pref[gm * EMB + kk + c] : 0.f;
        }
        #pragma unroll
        for (int e = tid; e < 16 * 64; e += 256) {
            int r = e >> 6, c = e & 63;
            Bs[r][c] = W[(kk + r) * HDIM + n0 + c];
        }
        __syncthreads();
        #pragma unroll
        for (int k = 0; k < 16; ++k) {
            float a[4], b[4];
            #pragma unroll
            for (int q = 0; q < 4; ++q) { a[q] = As[ty * 4 + q][k]; b[q] = Bs[k][tx * 4 + q]; }
            #pragma unroll
            for (int i = 0; i < 4; ++i)
                #pragma unroll
                for (int j = 0; j < 4; ++j)
                    acc[i][j] = fmaf(a[i], b[j], acc[i][j]);
        }
        __syncthreads();
    }
    #pragma unroll
    for (int i = 0; i < 4; ++i) {
        int gm = m0 + ty * 4 + i;
        if (gm <= N_TOK)
            #pragma unroll
            for (int j = 0; j < 4; ++j)
                g_P[gm * HDIM + n0 + tx * 4 + j] = acc[i][j];
    }
}

// ---------------------------------------------------------------------------
// Big GEMM, 128x256 tile, K=1024 (bf16 tcgen05 / fp32 SIMT fallback).
// MODE 2: A = h1 fused from P; epilogue relu(+b2) -> g_h2b (bf16)
// MODE 3: A = g_h2b; epilogue bias+feats+relu, dot W_s2 -> g_part
// Tensor path: K-chunk 64 (bf16 = 128B rows, SW128), 2-stage ring,
//              two N=128 MMAs per k-step (D0 cols 0-127, D1 cols 128-255).
// ---------------------------------------------------------------------------
template <int MODE>
__global__ __launch_bounds__(256, 2)
void k_gemm_big(const float* __restrict__ W,               // fp32 [K][N] (fallback)
                const __nv_bfloat16* __restrict__ Bt,      // bf16 [N][K] (tensor)
                const float* __restrict__ bias1,           // b_dan1 (MODE 2)
                const float* __restrict__ bias2,           // b_dan2 / b_s1
                const float* __restrict__ Ws2)             // MODE 3
{
#if HAS_TCGEN05
    // ======================= tcgen05 bf16 path =======================
    extern __shared__ __align__(1024) char dyn[];
    // layout: A stage0 @0 (16KB), A stage1 @16K, B stage0 @32K (32KB), B stage1 @64K
    char* sA[2] = { dyn,          dyn + 16384 };
    char* sB[2] = { dyn + 32768,  dyn + 65536 };

    __shared__ float sepi[5 * 256];
    __shared__ int   s_x[128];
    __shared__ int   s_y[128];
    __shared__ float s_inv[128];
    __shared__ __align__(8) unsigned long long s_mbar[2];
    __shared__ uint32_t s_tmemptr;

    const int tid = threadIdx.x;
    const int m0 = blockIdx.x * 128, n0 = blockIdx.y * 256;

    if (tid < 32) {
        TC_ALLOC(smem_u32(&s_tmemptr), 256);
        TC_RELINQ();
    }
    if (tid == 0) {
        MBAR_INIT(smem_u32(&s_mbar[0]), 1);
        MBAR_INIT(smem_u32(&s_mbar[1]), 1);
    }

    if (MODE == 2) {
        if (tid < 256) sepi[tid] = bias2[n0 + tid];
    } else {
        for (int e = tid; e < 256; e += 256) {
            sepi[e]        = bias2[n0 + e];
            sepi[256 + e]  = g_wf[n0 + e];
            sepi[512 + e]  = g_wf[HDIM + n0 + e];
            sepi[768 + e]  = g_wf[2 * HDIM + n0 + e];
            sepi[1024 + e] = Ws2[n0 + e];
        }
    }
    if (tid < 128) {
        int s = m0 + tid; if (s >= NSPAN) s = NSPAN - 1;
        if (MODE == 2) {
            int i_ = g_si[s], j_ = g_sj[s];
            s_x[tid] = j_ + 1; s_y[tid] = i_;
            s_inv[tid] = 1.0f / (float)(j_ - i_ + 1);
        } else {
            s_x[tid] = s;
        }
    }
    __syncthreads();
    const uint32_t tmem  = s_tmemptr;
    const uint32_t mbar0 = smem_u32(&s_mbar[0]);
    const uint32_t mbar1 = smem_u32(&s_mbar[1]);
    const uint64_t adesc[2] = { make_desc(smem_u32(sA[0])), make_desc(smem_u32(sA[1])) };
    const uint64_t bdesc[2] = { make_desc(smem_u32(sB[0])), make_desc(smem_u32(sB[1])) };

    int ph[2] = {0, 0};
    #pragma unroll 1
    for (int c = 0; c < 16; ++c) {
        const int st = c & 1;
        if (c >= 2) {
            MBAR_WAIT_PARITY(st ? mbar1 : mbar0, ph[st]);
            ph[st] ^= 1;
        }
        const int kk = c * 64;
        // A tile: 128 rows x 64 k bf16 (16KB), 1024 16B-units, 4 per thread
        #pragma unroll
        for (int u = 0; u < 4; ++u) {
            int idx = tid + u * 256;
            int r = idx >> 3;
            int kc = (idx & 7) * 8;            // element offset within chunk
            int byte = r * 128 + kc * 2;
            int sw = byte ^ ((byte >> 3) & 0x70);
            uint4 o;
            if (MODE == 2) {
                const float* pe = g_P + (size_t)s_x[r] * HDIM + kk + kc;
                const float* pi = g_P + (size_t)s_y[r] * HDIM + kk + kc;
                const float* bb = bias1 + kk + kc;
                float inv = s_inv[r];
                float4 e0 = *(const float4*)pe, e1 = *(const float4*)(pe + 4);
                float4 i0 = *(const float4*)pi, i1 = *(const float4*)(pi + 4);
                float4 b0 = *(const float4*)bb, b1 = *(const float4*)(bb + 4);
                float v0 = fmaxf(fmaf(e0.x - i0.x, inv, b0.x), 0.f);
                float v1 = fmaxf(fmaf(e0.y - i0.y, inv, b0.y), 0.f);
                float v2 = fmaxf(fmaf(e0.z - i0.z, inv, b0.z), 0.f);
                float v3 = fmaxf(fmaf(e0.w - i0.w, inv, b0.w), 0.f);
                float v4 = fmaxf(fmaf(e1.x - i1.x, inv, b1.x), 0.f);
                float v5 = fmaxf(fmaf(e1.y - i1.y, inv, b1.y), 0.f);
                float v6 = fmaxf(fmaf(e1.z - i1.z, inv, b1.z), 0.f);
                float v7 = fmaxf(fmaf(e1.w - i1.w, inv, b1.w), 0.f);
                o.x = pack_bf16(v0, v1); o.y = pack_bf16(v2, v3);
                o.z = pack_bf16(v4, v5); o.w = pack_bf16(v6, v7);
            } else {
                o = *(const uint4*)(g_h2b + (size_t)s_x[r] * HDIM + kk + kc);
            }
            *(uint4*)(sA[st] + sw) = o;
        }
        // B tile: 256 rows x 64 k bf16 (32KB), 2048 units, 8 per thread
        #pragma unroll
        for (int u = 0; u < 8; ++u) {
            int idx = tid + u * 256;
            int r = idx >> 3;
            int kc = (idx & 7) * 8;
            int byte = r * 128 + kc * 2;
            int sw = byte ^ ((byte >> 3) & 0x70);
            uint4 w = *(const uint4*)(Bt + (size_t)(n0 + r) * HDIM + kk + kc);
            *(uint4*)(sB[st] + sw) = w;
        }
        __syncthreads();
        if (tid == 0) {
            FENCE_ASYNC_SHARED();
            #pragma unroll
            for (int stp = 0; stp < 4; ++stp) {
                bool acc = (c > 0) || (stp > 0);
                mma_bf16_ss(tmem,       adesc[st] + stp * 2, bdesc[st] + stp * 2,        IDESC_BF16, acc);
                mma_bf16_ss(tmem + 128, adesc[st] + stp * 2, bdesc[st] + 1024 + stp * 2, IDESC_BF16, acc);
            }
            TC_COMMIT(st ? mbar1 : mbar0);
        }
    }
    MBAR_WAIT_PARITY(mbar0, ph[0]);
    MBAR_WAIT_PARITY(mbar1, ph[1]);
    TC_FENCE_AFTER();

    // epilogue: warps 0-3, lane = row; D in TMEM cols 0..255
    if (tid < 128) {
        if (MODE == 2) {
            int gs = m0 + tid;
            bool ok = gs < NSPAN;
            __nv_bfloat16* orow = g_h2b + (size_t)(ok ? gs : 0) * HDIM + n0;
            #pragma unroll 1
            for (int nb = 0; nb < 8; ++nb) {
                uint32_t r[32];
                TC_LD_X32(r, tmem + nb * 32);
                TC_WAIT_LD();
                if (ok) {
                    uint4 o0, o1;
                    uint32_t* po = &o0.x;
                    #pragma unroll
                    for (int q = 0; q < 32; q += 2) {
                        float a = fmaxf(__uint_as_float(r[q])     + sepi[nb * 32 + q],     0.f);
                        float b = fmaxf(__uint_as_float(r[q + 1]) + sepi[nb * 32 + q + 1], 0.f);
                        po[q >> 1] = pack_bf16(a, b);
                    }
                    *(uint4*)(orow + nb * 32)     = o0;
                    *(uint4*)(orow + nb * 32 + 8) = o1;
                }
            }
        } else {
            int gs = m0 + tid;
            int sc = (gs < NSPAN) ? gs : (NSPAN - 1);
            int i_ = g_si[sc], j_ = g_sj[sc];
            float fl = (float)(j_ - i_ + 1);
            float fi = (float)i_;
            float fe = (float)(j_ + 1);
            float sum = 0.f;
            #pragma unroll 1
            for (int nb = 0; nb < 8; ++nb) {
                uint32_t r[32];
                TC_LD_X32(r, tmem + nb * 32);
                TC_WAIT_LD();
                #pragma unroll
                for (int q = 0; q < 32; ++q) {
                    int n = nb * 32 + q;
                    float v = __uint_as_float(r[q]) + sepi[n];
                    v = fmaf(fl, sepi[256 + n], v);
                    v = fmaf(fi, sepi[512 + n], v);
                    v = fmaf(fe, sepi[768 + n], v);
                    v = fmaxf(v, 0.f);
                    sum = fmaf(v, sepi[1024 + n], sum);
                }
            }
            g_part[(size_t)blockIdx.y * NSPAN_PAD + m0 + tid] = sum;
        }
    }
    __syncthreads();
    if (tid == 0) { MBAR_INVAL(mbar0); MBAR_INVAL(mbar1); }
    __syncthreads();
    if (tid < 32) TC_DEALLOC(tmem, 256);

#else
    // ======================= SIMT fp32 fallback (two 128-wide halves) ==========
    __shared__ __align__(16) float sh[2304];
    float* As = sh;
    float* Bs = sh + 1024;

    int tid = threadIdx.x;
    int tx = tid % 16, ty = tid / 16;
    int m0 = blockIdx.x * 128;

    int lm, lkh;
    int xe = 0, yi = 0;
    float invlen = 0.f;
    int sA_ = 0;
    if (MODE == 2) {
        lm = tid & 127; lkh = tid >> 7;
        int s = m0 + lm; if (s >= NSPAN) s = NSPAN - 1;
        int i_ = g_si[s], j_ = g_sj[s];
        invlen = 1.0f / (float)(j_ - i_ + 1);
        xe = j_ + 1; yi = i_;
    } else {
        lm = tid >> 1; lkh = tid & 1;
        sA_ = m0 + lm; if (sA_ >= NSPAN) sA_ = NSPAN - 1;
    }

    int br = tid >> 5;
    int bc = (tid & 31) << 2;

    float rs_tot[8] = {};

    #pragma unroll 1
    for (int nh = 0; nh < 2; ++nh) {
        int n0 = blockIdx.y * 256 + nh * 128;

        float acc[8][8];
        #pragma unroll
        for (int a = 0; a < 8; ++a)
            #pragma unroll
            for (int b = 0; b < 8; ++b) acc[a][b] = 0.f;

        for (int kk = 0; kk < HDIM; kk += 8) {
            if (MODE == 2) {
                const float4 pe = *(const float4*)(g_P + (size_t)xe * HDIM + kk + lkh * 4);
                const float4 pi = *(const float4*)(g_P + (size_t)yi * HDIM + kk + lkh * 4);
                const float4 bb = *(const float4*)(bias1 + kk + lkh * 4);
                As[(lkh * 4 + 0) * 128 + lm] = fmaxf(fmaf(pe.x - pi.x, invlen, bb.x), 0.f);
                As[(lkh * 4 + 1) * 128 + lm] = fmaxf(fmaf(pe.y - pi.y, invlen, bb.y), 0.f);
                As[(lkh * 4 + 2) * 128 + lm] = fmaxf(fmaf(pe.z - pi.z, invlen, bb.z), 0.f);
                As[(lkh * 4 + 3) * 128 + lm] = fmaxf(fmaf(pe.w - pi.w, invlen, bb.w), 0.f);
            } else {
                const __nv_bfloat16* ar = g_h2b + (size_t)sA_ * HDIM + kk + lkh * 4;
                As[(lkh * 4 + 0) * 128 + lm] = __bfloat162float(ar[0]);
                As[(lkh * 4 + 1) * 128 + lm] = __bfloat162float(ar[1]);
                As[(lkh * 4 + 2) * 128 + lm] = __bfloat162float(ar[2]);
                As[(lkh * 4 + 3) * 128 + lm] = __bfloat162float(ar[3]);
            }
            *(float4*)(Bs + br * 128 + bc) = *(const float4*)(W + (size_t)(kk + br) * HDIM + n0 + bc);
            __syncthreads();

            #pragma unroll
            for (int k = 0; k < 8; ++k) {
                float a[8], b[8];
                float4 t;
                t = *(const float4*)(As + k * 128 + (ty << 2));      a[0]=t.x; a[1]=t.y; a[2]=t.z; a[3]=t.w;
                t = *(const float4*)(As + k * 128 + (ty << 2) + 64); a[4]=t.x; a[5]=t.y; a[6]=t.z; a[7]=t.w;
                t = *(const float4*)(Bs + k * 128 + (tx << 2));      b[0]=t.x; b[1]=t.y; b[2]=t.z; b[3]=t.w;
                t = *(const float4*)(Bs + k * 128 + (tx << 2) + 64); b[4]=t.x; b[5]=t.y; b[6]=t.z; b[7]=t.w;
                #pragma unroll
                for (int ii = 0; ii < 8; ++ii)
                    #pragma unroll
                    for (int jj = 0; jj < 8; ++jj)
                        acc[ii][jj] = fmaf(a[ii], b[jj], acc[ii][jj]);
            }
            __syncthreads();
        }

        if (MODE == 2) {
            float cb[8];
            #pragma unroll
            for (int q = 0; q < 4; ++q) {
                cb[q]     = bias2[n0 + (tx << 2) + q];
                cb[4 + q] = bias2[n0 + (tx << 2) + 64 + q];
            }
            #pragma unroll
            for (int ri = 0; ri < 8; ++ri) {
                int r = (ri < 4) ? ((ty << 2) + ri) : (64 + (ty << 2) + ri - 4);
                int gs = m0 + r;
                if (gs < NSPAN) {
                    #pragma unroll
                    for (int q = 0; q < 4; ++q) {
                        g_h2b[(size_t)gs * HDIM + n0 + (tx << 2) + q] =
                            __float2bfloat16(fmaxf(acc[ri][q] + cb[q], 0.f));
                        g_h2b[(size_t)gs * HDIM + n0 + (tx << 2) + 64 + q] =
                            __float2bfloat16(fmaxf(acc[ri][4 + q] + cb[4 + q], 0.f));
                    }
                }
            }
        } else {
            int cbase = n0 + (tx << 2);
            float cb[8], cl[8], ci[8], ce[8], cw[8];
            #pragma unroll
            for (int q = 0; q < 4; ++q) {
                int c0 = cbase + q, c1 = cbase + 64 + q;
                cb[q] = bias2[c0];             cb[4+q] = bias2[c1];
                cl[q] = g_wf[c0];              cl[4+q] = g_wf[c1];
                ci[q] = g_wf[HDIM + c0];       ci[4+q] = g_wf[HDIM + c1];
                ce[q] = g_wf[2*HDIM + c0];     ce[4+q] = g_wf[2*HDIM + c1];
                cw[q] = Ws2[c0];               cw[4+q] = Ws2[c1];
            }
            #pragma unroll
            for (int ri = 0; ri < 8; ++ri) {
                int r = (ri < 4) ? ((ty << 2) + ri) : (64 + (ty << 2) + ri - 4);
                int gs = m0 + r; int sc = (gs < NSPAN) ? gs : (NSPAN - 1);
                int ii_ = g_si[sc], jj_ = g_sj[sc];
                float fl = (float)(jj_ - ii_ + 1);
                float fi = (float)ii_;
                float fe = (float)(jj_ + 1);
                float sum = 0.f;
                #pragma unroll
                for (int cc = 0; cc < 8; ++cc) {
                    float v = acc[ri][cc] + cb[cc];
                    v = fmaf(fl, cl[cc], v);
                    v = fmaf(fi, ci[cc], v);
                    v = fmaf(fe, ce[cc], v);
                    v = fmaxf(v, 0.f);
                    sum = fmaf(v, cw[cc], sum);
                }
                rs_tot[ri] += sum;
            }
        }
    }

    if (MODE == 3) {
        #pragma unroll
        for (int ri = 0; ri < 8; ++ri) {
            int r = (ri < 4) ? ((ty << 2) + ri) : (64 + (ty << 2) + ri - 4);
            sh[r * 17 + tx] = rs_tot[ri];
        }
        __syncthreads();
        if (tid < 128) {
            float t = 0.f;
            #pragma unroll
            for (int q = 0; q < 16; ++q) t += sh[tid * 17 + q];
            g_part[(size_t)blockIdx.y * NSPAN_PAD + m0 + tid] = t;
        }
    }
#endif
}

// ---------------------------------------------------------------------------
// Final reduce (4 column-block partials)
// ---------------------------------------------------------------------------
__global__ void k_final(const float* __restrict__ b_s2, float* __restrict__ out)
{
    int s = blockIdx.x * blockDim.x + threadIdx.x;
    if (s < NSPAN) {
        float t = b_s2[0];
        #pragma unroll
        for (int q = 0; q < 4; ++q) t += g_part[(size_t)q * NSPAN_PAD + s];
        out[s] = t;
    }
}

// ---------------------------------------------------------------------------
extern "C" void kernel_launch(void* const* d_in, const int* in_sizes, int n_in,
                              void* d_out, int out_size)
{
    const int*   sent    = (const int*)d_in[0];
    const int*   pos     = (const int*)d_in[1];
    const float* We_wrd  = (const float*)d_in[2];
    const float* We_pos  = (const float*)d_in[3];
    const float* W_dan1  = (const float*)d_in[4];
    const float* b_dan1  = (const float*)d_in[5];
    const float* W_dan2  = (const float*)d_in[6];
    const float* b_dan2  = (const float*)d_in[7];
    const float* W_s1    = (const float*)d_in[8];
    const float* b_s1    = (const float*)d_in[9];
    const float* W_s2    = (const float*)d_in[10];
    const float* b_s2    = (const float*)d_in[11];
    float* out = (float*)d_out;

    __nv_bfloat16* wt2b;  cudaGetSymbolAddress((void**)&wt2b,  g_Wt2b);
    __nv_bfloat16* ws1tb; cudaGetSymbolAddress((void**)&ws1tb, g_Ws1tb);

    static bool attr_done = false;
    if (!attr_done) {
        cudaFuncSetAttribute((const void*)k_gemm_big<2>,
                             cudaFuncAttributeMaxDynamicSharedMemorySize, 98304);
        cudaFuncSetAttribute((const void*)k_gemm_big<3>,
                             cudaFuncAttributeMaxDynamicSharedMemorySize, 98304);
        attr_done = true;
    }

    k_pref <<<4, 256>>>(sent, pos, We_wrd, We_pos);
    k_spans<<<N_TOK, 256>>>();
    k_wfeat<<<4, 256>>>(W_s1);
    k_transp<<<dim3(32, 32), dim3(32, 8)>>>(W_dan2, wt2b);
    k_transp<<<dim3(32, 32), dim3(32, 8)>>>(W_s1, ws1tb);
    k_gemmP<<<dim3(7, 16), 256>>>(W_dan1);
    k_gemm_big<2><<<dim3(MTILES, 4), 256, 98304>>>(W_dan2, wt2b,  b_dan1, b_dan2, nullptr);
    k_gemm_big<3><<<dim3(MTILES, 4), 256, 98304>>>(W_s1,   ws1tb, nullptr, b_s1,  W_s2);
    k_final<<<(NSPAN + 255) / 256, 256>>>(b_s2, out);
}

// round 5
// speedup vs baseline: 6.4650x; 1.0549x over previous
#include <cuda_runtime.h>
#include <cuda_bf16.h>
#include <cuda_fp8.h>
#include <cstdint>

// Problem constants
#define N_TOK   384
#define WDIM    512
#define EMB     1024
#define HDIM    1024
#define NSPAN   73920
#define MTILES  578
#define NSPAN_PAD (MTILES*128)

// Arch gate: tcgen05 only exists in arch-specific (sm_103a) device passes.
#if defined(__CUDA_ARCH__) && (__CUDA_ARCH__ >= 1000) && defined(__CUDA_ARCH_FEAT_SM103_ALL)
#define HAS_TCGEN05 1
#else
#define HAS_TCGEN05 0
#endif

// Storage scaling: h (A operands) stored x2^8, weights (B) stored x2^6.
// Tensor path compensates via ue8m0 block scales (2^-8 / 2^-6);
// fallback compensates with fp32 multipliers.
#define H_SCALE   256.0f
#define H_INV     (1.0f/256.0f)
#define W_SCALE   64.0f
#define W_INV     (1.0f/64.0f)

// Scratch
__device__ float g_pref[(N_TOK + 1) * EMB];
__device__ float g_P[(N_TOK + 1) * HDIM];
__device__ uint8_t g_h2f8[(size_t)NSPAN * HDIM];   // h2 * 2^8, e4m3 (75MB)
__device__ int   g_si[NSPAN_PAD];
__device__ int   g_sj[NSPAN_PAD];
__device__ float g_wf[3 * HDIM];
__device__ float g_part[(size_t)8 * NSPAN_PAD];
__device__ uint8_t g_Wt2f8[HDIM * HDIM];    // (W_dan2^T)*2^6  [n][k] e4m3
__device__ uint8_t g_Ws1tf8[HDIM * HDIM];   // (W_s1[:1024]^T)*2^6 [n][k] e4m3

#if HAS_TCGEN05
// ---------------------------------------------------------------------------
// PTX helpers (tcgen05 path only)
// ---------------------------------------------------------------------------
__device__ __forceinline__ uint32_t smem_u32(const void* p) {
    uint32_t a;
    asm("{ .reg .u64 t; cvta.to.shared.u64 t, %1; cvt.u32.u64 %0, t; }" : "=r"(a) : "l"(p));
    return a;
}

// pack two fp32 -> e4m3x2 (lo in low byte)
__device__ __forceinline__ uint32_t pack_e4m3x2(float lo, float hi) {
    uint16_t h;
    asm("cvt.rn.satfinite.e4m3x2.f32 %0, %1, %2;" : "=h"(h) : "f"(hi), "f"(lo));
    return (uint32_t)h;
}

#define MBAR_INIT(addr, cnt) \
    asm volatile("mbarrier.init.shared.b64 [%0], %1;" :: "r"(addr), "r"(cnt) : "memory")
#define MBAR_INVAL(addr) \
    asm volatile("mbarrier.inval.shared.b64 [%0];" :: "r"(addr) : "memory")

#define MBAR_WAIT_PARITY(addr, parity) do {                                        \
    uint32_t _m = (addr); uint32_t _p = (parity); uint32_t _done;                  \
    asm volatile("{\n\t.reg .pred p;\n\t"                                          \
        "mbarrier.try_wait.parity.acquire.cta.shared::cta.b64 p, [%1], %2;\n\t"    \
        "selp.b32 %0, 1, 0, p;\n\t}"                                               \
        : "=r"(_done) : "r"(_m), "r"(_p) : "memory");                              \
    if (!_done) {                                                                  \
        asm volatile("{\n\t.reg .pred P1;\n\t"                                     \
            "WL_%=:\n\t"                                                           \
            "mbarrier.try_wait.parity.acquire.cta.shared::cta.b64 P1, [%0], %1, 0x989680;\n\t" \
            "@P1 bra.uni WD_%=;\n\t"                                               \
            "bra.uni WL_%=;\n\t"                                                   \
            "WD_%=:\n\t}"                                                          \
            :: "r"(_m), "r"(_p) : "memory");                                       \
    }                                                                              \
} while (0)

#define TC_ALLOC(smem_addr, ncols) \
    asm volatile("tcgen05.alloc.cta_group::1.sync.aligned.shared::cta.b32 [%0], %1;" \
        :: "r"((uint32_t)(smem_addr)), "r"((uint32_t)(ncols)) : "memory")
#define TC_DEALLOC(tmem, ncols) \
    asm volatile("tcgen05.dealloc.cta_group::1.sync.aligned.b32 %0, %1;" \
        :: "r"(tmem), "r"((uint32_t)(ncols)))
#define TC_RELINQ() \
    asm volatile("tcgen05.relinquish_alloc_permit.cta_group::1.sync.aligned;")
#define TC_COMMIT(mbar) \
    asm volatile("tcgen05.commit.cta_group::1.mbarrier::arrive::one.shared::cluster.b64 [%0];" \
        :: "r"((uint32_t)(mbar)) : "memory")
#define TC_FENCE_BEFORE() asm volatile("tcgen05.fence::before_thread_sync;" ::: "memory")
#define TC_FENCE_AFTER()  asm volatile("tcgen05.fence::after_thread_sync;" ::: "memory")
#define TC_WAIT_LD()      asm volatile("tcgen05.wait::ld.sync.aligned;" ::: "memory")
#define TC_WAIT_ST()      asm volatile("tcgen05.wait::st.sync.aligned;" ::: "memory")
#define FENCE_ASYNC_SHARED() asm volatile("fence.proxy.async.shared::cta;" ::: "memory")

#define TC_ST_X1(tmem_addr, r0) \
    asm volatile("tcgen05.st.sync.aligned.32x32b.x1.b32 [%0], {%1};" \
        :: "r"(tmem_addr), "r"(r0) : "memory")

#define TC_LD_X32(r, tmem_addr) \
    asm volatile("tcgen05.ld.sync.aligned.32x32b.x32.b32 " \
        "{%0, %1, %2, %3, %4, %5, %6, %7, %8, %9, %10, %11, %12, %13, %14, %15, " \
        " %16, %17, %18, %19, %20, %21, %22, %23, %24, %25, %26, %27, %28, %29, %30, %31}, [%32];" \
        : "=r"((r)[0]),  "=r"((r)[1]),  "=r"((r)[2]),  "=r"((r)[3]), \
          "=r"((r)[4]),  "=r"((r)[5]),  "=r"((r)[6]),  "=r"((r)[7]), \
          "=r"((r)[8]),  "=r"((r)[9]),  "=r"((r)[10]), "=r"((r)[11]), \
          "=r"((r)[12]), "=r"((r)[13]), "=r"((r)[14]), "=r"((r)[15]), \
          "=r"((r)[16]), "=r"((r)[17]), "=r"((r)[18]), "=r"((r)[19]), \
          "=r"((r)[20]), "=r"((r)[21]), "=r"((r)[22]), "=r"((r)[23]), \
          "=r"((r)[24]), "=r"((r)[25]), "=r"((r)[26]), "=r"((r)[27]), \
          "=r"((r)[28]), "=r"((r)[29]), "=r"((r)[30]), "=r"((r)[31]) \
        : "r"(tmem_addr))

// SW128 K-major SMEM descriptor (LBO=1, SBO=64, version=1, layout=2)
static constexpr uint64_t DESC_BASE_SW128 =
    (uint64_t(2) << 61) | (uint64_t(1) << 46) | (uint64_t(64) << 32) | (uint64_t(1) << 16);
__device__ __forceinline__ uint64_t make_desc(uint32_t addr) {
    return DESC_BASE_SW128 | ((uint64_t)(addr >> 4) & 0x3FFF);
}

// Block-scaled MXFP8 SS MMA, cta_group::1 (validated pattern)
__device__ __forceinline__ void mma_mxf8_ss(uint32_t d, uint64_t ad, uint64_t bd,
                                            uint32_t idesc, uint32_t sca, uint32_t scb,
                                            bool acc) {
    uint32_t en = acc ? 1u : 0u;
    asm volatile(
        "{\n\t.reg .pred p;\n\t"
        "setp.ne.u32 p, %6, 0;\n\t"
        "tcgen05.mma.cta_group::1.kind::mxf8f6f4.block_scale.scale_vec::1X "
        "[%0], %1, %2, %3, [%4], [%5], p;\n\t"
        "}"
        :: "r"(d), "l"(ad), "l"(bd), "r"(idesc), "r"(sca), "r"(scb), "r"(en)
        : "memory");
}
// idesc mxf8f6f4: M=128 -> bits[27:28]=1, UE8M0 -> bit23, N=128 -> (128/8)<<17,
// atype=btype=E4M3 (0), SFA_ID=SFB_ID=0
#define IDESC_MXF8 ((1u<<27)|(1u<<23)|(16u<<17))

// TMEM layout: D0 @0 (128 cols), D1 @128, SCA @256 (4 cols), SCB @260 (8 cols)
#define TM_D0   0
#define TM_D1   128
#define TM_SCA  256
#define TM_SCB  260
#endif  // HAS_TCGEN05

// ---------------------------------------------------------------------------
// Kernel: embedding prefix sums
// ---------------------------------------------------------------------------
__global__ void k_pref(const int* __restrict__ sent, const int* __restrict__ pos,
                       const float* __restrict__ We_wrd, const float* __restrict__ We_pos)
{
    int c = blockIdx.x * blockDim.x + threadIdx.x;
    if (c >= EMB) return;
    bool isPos = (c < WDIM);
    const float* base = isPos ? (We_pos + c) : (We_wrd + (c - WDIM));
    const int*   idx  = isPos ? pos : sent;
    float run = 0.f;
    g_pref[c] = 0.f;
    #pragma unroll 4
    for (int t = 0; t < N_TOK; ++t) {
        run += base[(size_t)idx[t] * WDIM];
        g_pref[(t + 1) * EMB + c] = run;
    }
}

// ---------------------------------------------------------------------------
// Kernel: span tables
// ---------------------------------------------------------------------------
__global__ void k_spans()
{
    int i = blockIdx.x;
    int base = i * N_TOK - (i * (i - 1)) / 2;
    for (int j = i + threadIdx.x; j < N_TOK; j += blockDim.x) {
        int s = base + (j - i);
        g_si[s] = i;
        g_sj[s] = j;
    }
    if (blockIdx.x == 0) {
        for (int s = NSPAN + threadIdx.x; s < NSPAN_PAD; s += blockDim.x) {
            g_si[s] = 0; g_sj[s] = 0;
        }
    }
}

// ---------------------------------------------------------------------------
// Kernel: feat weight folding
// ---------------------------------------------------------------------------
__global__ void k_wfeat(const float* __restrict__ W_s1)
{
    int n = blockIdx.x * blockDim.x + threadIdx.x;
    if (n >= HDIM) return;
    float sl = 0.f, si = 0.f, se = 0.f;
    #pragma unroll
    for (int r = 0; r < 16; ++r) {
        sl += W_s1[(HDIM +      r) * HDIM + n];
        si += W_s1[(HDIM + 16 + r) * HDIM + n];
        se += W_s1[(HDIM + 32 + r) * HDIM + n];
    }
    g_wf[n] = sl; g_wf[HDIM + n] = si; g_wf[2 * HDIM + n] = se;
}

// ---------------------------------------------------------------------------
// Kernel: 1024x1024 transpose + fp32 -> e4m3 (scaled x64)
// ---------------------------------------------------------------------------
__global__ void k_transp(const float* __restrict__ src, uint8_t* __restrict__ dst)
{
    __shared__ float t[32][33];
    int x = blockIdx.x * 32 + threadIdx.x;
    int y = blockIdx.y * 32 + threadIdx.y;
    #pragma unroll
    for (int j = 0; j < 32; j += 8)
        t[threadIdx.y + j][threadIdx.x] = src[(size_t)(y + j) * HDIM + x];
    __syncthreads();
    x = blockIdx.y * 32 + threadIdx.x;
    y = blockIdx.x * 32 + threadIdx.y;
    #pragma unroll
    for (int j = 0; j < 32; j += 8) {
        __nv_fp8_e4m3 v(t[threadIdx.x][threadIdx.y + j] * W_SCALE);
        dst[(size_t)(y + j) * HDIM + x] = *reinterpret_cast<uint8_t*>(&v);
    }
}

// ---------------------------------------------------------------------------
// Kernel: P = pref @ W_dan1  (64x64 tiles, 4x4/thread) fp32
// ---------------------------------------------------------------------------
__global__ __launch_bounds__(256) void k_gemmP(const float* __restrict__ W)
{
    __shared__ float As[64][17];
    __shared__ float Bs[16][68];
    int tid = threadIdx.x;
    int tx = tid % 16, ty = tid / 16;
    int m0 = blockIdx.x * 64, n0 = blockIdx.y * 64;
    float acc[4][4] = {};

    for (int kk = 0; kk < EMB; kk += 16) {
        #pragma unroll
        for (int e = tid; e < 64 * 16; e += 256) {
            int r = e >> 4, c = e & 15;
            int gm = m0 + r;
            As[r][c] = (gm <= N_TOK) ? g_pref[gm * EMB + kk + c] : 0.f;
        }
        #pragma unroll
        for (int e = tid; e < 16 * 64; e += 256) {
            int r = e >> 6, c = e & 63;
            Bs[r][c] = W[(kk + r) * HDIM + n0 + c];
        }
        __syncthreads();
        #pragma unroll
        for (int k = 0; k < 16; ++k) {
            float a[4], b[4];
            #pragma unroll
            for (int q = 0; q < 4; ++q) { a[q] = As[ty * 4 + q][k]; b[q] = Bs[k][tx * 4 + q]; }
            #pragma unroll
            for (int i = 0; i < 4; ++i)
                #pragma unroll
                for (int j = 0; j < 4; ++j)
                    acc[i][j] = fmaf(a[i], b[j], acc[i][j]);
        }
        __syncthreads();
    }
    #pragma unroll
    for (int i = 0; i < 4; ++i) {
        int gm = m0 + ty * 4 + i;
        if (gm <= N_TOK)
            #pragma unroll
            for (int j = 0; j < 4; ++j)
                g_P[gm * HDIM + n0 + tx * 4 + j] = acc[i][j];
    }
}

// ---------------------------------------------------------------------------
// Big GEMM, 128x256 tile, K=1024 (mxfp8 tcgen05 / fp32 SIMT fallback).
// MODE 2: A = h1 fused from P (x2^8 e4m3); epilogue relu(+b2) -> g_h2f8 (x2^8)
// MODE 3: A = g_h2f8; epilogue bias+feats+relu, dot W_s2 -> g_part
// Tensor path: K-chunk 128 fp8 (128B rows, SW128), 2-stage ring,
//              per chunk 4 K-steps x two N=128 MMAs. Block scales 2^-8 / 2^-6.
// ---------------------------------------------------------------------------
template <int MODE>
__global__ __launch_bounds__(256, 2)
void k_gemm_big(const float* __restrict__ W,          // fp32 [K][N] (fallback)
                const uint8_t* __restrict__ Bt,       // e4m3 [N][K] x2^6 (tensor)
                const float* __restrict__ bias1,      // b_dan1 (MODE 2)
                const float* __restrict__ bias2,      // b_dan2 / b_s1
                const float* __restrict__ Ws2)        // MODE 3
{
#if HAS_TCGEN05
    // ======================= tcgen05 mxfp8 path =======================
    extern __shared__ __align__(1024) char dyn[];
    // A stage0 @0 (16KB), A stage1 @16K, B stage0 @32K (32KB), B stage1 @64K
    char* sA[2] = { dyn,          dyn + 16384 };
    char* sB[2] = { dyn + 32768,  dyn + 65536 };

    __shared__ float sepi[5 * 256];
    __shared__ int   s_x[128];
    __shared__ int   s_y[128];
    __shared__ float s_inv[128];
    __shared__ __align__(8) unsigned long long s_mbar[2];
    __shared__ uint32_t s_tmemptr;

    const int tid = threadIdx.x;
    const int m0 = blockIdx.x * 128, n0 = blockIdx.y * 256;

    if (tid < 32) {
        TC_ALLOC(smem_u32(&s_tmemptr), 512);
        TC_RELINQ();
    }
    if (tid == 0) {
        MBAR_INIT(smem_u32(&s_mbar[0]), 1);
        MBAR_INIT(smem_u32(&s_mbar[1]), 1);
    }

    if (MODE == 2) {
        if (tid < 256) sepi[tid] = bias2[n0 + tid];
    } else {
        for (int e = tid; e < 256; e += 256) {
            sepi[e]        = bias2[n0 + e];
            sepi[256 + e]  = g_wf[n0 + e];
            sepi[512 + e]  = g_wf[HDIM + n0 + e];
            sepi[768 + e]  = g_wf[2 * HDIM + n0 + e];
            sepi[1024 + e] = Ws2[n0 + e];
        }
    }
    if (tid < 128) {
        int s = m0 + tid; if (s >= NSPAN) s = NSPAN - 1;
        if (MODE == 2) {
            int i_ = g_si[s], j_ = g_sj[s];
            s_x[tid] = j_ + 1; s_y[tid] = i_;
            s_inv[tid] = 1.0f / (float)(j_ - i_ + 1);
        } else {
            s_x[tid] = s;
        }
    }
    __syncthreads();
    const uint32_t tmem  = s_tmemptr;

    // Block scales: SCA = 2^-8 (0x77), SCB = 2^-6 (0x79), all K-step bytes equal.
    if (tid < 128) {
        uint32_t wo = ((uint32_t)(tid & 127) >> 5) << 21;
        #pragma unroll
        for (int cix = 0; cix < 4; ++cix) {
            TC_ST_X1(tmem + TM_SCA + cix + wo, 0x77777777u);
            TC_WAIT_ST();
        }
        #pragma unroll
        for (int cix = 0; cix < 8; ++cix) {
            TC_ST_X1(tmem + TM_SCB + cix + wo, 0x79797979u);
            TC_WAIT_ST();
        }
    }
    TC_FENCE_BEFORE();
    __syncthreads();

    const uint32_t mbar0 = smem_u32(&s_mbar[0]);
    const uint32_t mbar1 = smem_u32(&s_mbar[1]);
    const uint64_t adesc[2] = { make_desc(smem_u32(sA[0])), make_desc(smem_u32(sA[1])) };
    const uint64_t bdesc[2] = { make_desc(smem_u32(sB[0])), make_desc(smem_u32(sB[1])) };

    int ph[2] = {0, 0};
    #pragma unroll 1
    for (int c = 0; c < 8; ++c) {
        const int st = c & 1;
        if (c >= 2) {
            MBAR_WAIT_PARITY(st ? mbar1 : mbar0, ph[st]);
            ph[st] ^= 1;
        }
        const int kk = c * 128;
        // A tile: 128 rows x 128 fp8 (16KB) = 1024 16B units, 4/thread
        #pragma unroll
        for (int u = 0; u < 4; ++u) {
            int idx = tid + u * 256;
            int r = idx >> 3;
            int kc = (idx & 7) * 16;           // fp8-element offset within chunk
            int byte = r * 128 + kc;
            int sw = byte ^ ((byte >> 3) & 0x70);
            uint4 o;
            if (MODE == 2) {
                const float* pe = g_P + (size_t)s_x[r] * HDIM + kk + kc;
                const float* pi = g_P + (size_t)s_y[r] * HDIM + kk + kc;
                const float* bb = bias1 + kk + kc;
                float inv = s_inv[r];
                uint32_t w[4];
                #pragma unroll
                for (int g = 0; g < 4; ++g) {
                    float4 e4 = *(const float4*)(pe + g * 4);
                    float4 i4 = *(const float4*)(pi + g * 4);
                    float4 b4 = *(const float4*)(bb + g * 4);
                    float v0 = fmaxf(fmaf(e4.x - i4.x, inv, b4.x), 0.f) * H_SCALE;
                    float v1 = fmaxf(fmaf(e4.y - i4.y, inv, b4.y), 0.f) * H_SCALE;
                    float v2 = fmaxf(fmaf(e4.z - i4.z, inv, b4.z), 0.f) * H_SCALE;
                    float v3 = fmaxf(fmaf(e4.w - i4.w, inv, b4.w), 0.f) * H_SCALE;
                    w[g] = pack_e4m3x2(v0, v1) | (pack_e4m3x2(v2, v3) << 16);
                }
                o.x = w[0]; o.y = w[1]; o.z = w[2]; o.w = w[3];
            } else {
                o = *(const uint4*)(g_h2f8 + (size_t)s_x[r] * HDIM + kk + kc);
            }
            *(uint4*)(sA[st] + sw) = o;
        }
        // B tile: 256 rows x 128 fp8 (32KB) = 2048 units, 8/thread
        #pragma unroll
        for (int u = 0; u < 8; ++u) {
            int idx = tid + u * 256;
            int r = idx >> 3;
            int kc = (idx & 7) * 16;
            int byte = r * 128 + kc;
            int sw = byte ^ ((byte >> 3) & 0x70);
            uint4 w = *(const uint4*)(Bt + (size_t)(n0 + r) * HDIM + kk + kc);
            *(uint4*)(sB[st] + sw) = w;
        }
        __syncthreads();
        if (tid == 0) {
            FENCE_ASYNC_SHARED();
            if (c == 0) TC_FENCE_AFTER();
            #pragma unroll
            for (int stp = 0; stp < 4; ++stp) {
                bool acc = (c > 0) || (stp > 0);
                mma_mxf8_ss(tmem + TM_D0, adesc[st] + stp * 2, bdesc[st] + stp * 2,
                            IDESC_MXF8, tmem + TM_SCA, tmem + TM_SCB, acc);
                mma_mxf8_ss(tmem + TM_D1, adesc[st] + stp * 2, bdesc[st] + 1024 + stp * 2,
                            IDESC_MXF8, tmem + TM_SCA, tmem + TM_SCB + 4, acc);
            }
            TC_COMMIT(st ? mbar1 : mbar0);
        }
    }
    MBAR_WAIT_PARITY(mbar0, ph[0]);
    MBAR_WAIT_PARITY(mbar1, ph[1]);
    TC_FENCE_AFTER();

    // epilogue: warps 0-3, lane = row; D in TMEM cols 0..255 (true values)
    if (tid < 128) {
        if (MODE == 2) {
            int gs = m0 + tid;
            bool ok = gs < NSPAN;
            uint8_t* orow = g_h2f8 + (size_t)(ok ? gs : 0) * HDIM + n0;
            #pragma unroll 1
            for (int nb = 0; nb < 8; ++nb) {
                uint32_t r[32];
                TC_LD_X32(r, tmem + nb * 32);
                TC_WAIT_LD();
                if (ok) {
                    uint4 o;
                    uint32_t w[8];
                    #pragma unroll
                    for (int q = 0; q < 32; q += 4) {
                        float a0 = fmaxf(__uint_as_float(r[q + 0]) + sepi[nb * 32 + q + 0], 0.f) * H_SCALE;
                        float a1 = fmaxf(__uint_as_float(r[q + 1]) + sepi[nb * 32 + q + 1], 0.f) * H_SCALE;
                        float a2 = fmaxf(__uint_as_float(r[q + 2]) + sepi[nb * 32 + q + 2], 0.f) * H_SCALE;
                        float a3 = fmaxf(__uint_as_float(r[q + 3]) + sepi[nb * 32 + q + 3], 0.f) * H_SCALE;
                        w[q >> 2] = pack_e4m3x2(a0, a1) | (pack_e4m3x2(a2, a3) << 16);
                    }
                    o.x = w[0]; o.y = w[1]; o.z = w[2]; o.w = w[3];
                    *(uint4*)(orow + nb * 32) = o;
                    o.x = w[4]; o.y = w[5]; o.z = w[6]; o.w = w[7];
                    *(uint4*)(orow + nb * 32 + 16) = o;
                }
            }
        } else {
            int gs = m0 + tid;
            int sc = (gs < NSPAN) ? gs : (NSPAN - 1);
            int i_ = g_si[sc], j_ = g_sj[sc];
            float fl = (float)(j_ - i_ + 1);
            float fi = (float)i_;
            float fe = (float)(j_ + 1);
            float sum = 0.f;
            #pragma unroll 1
            for (int nb = 0; nb < 8; ++nb) {
                uint32_t r[32];
                TC_LD_X32(r, tmem + nb * 32);
                TC_WAIT_LD();
                #pragma unroll
                for (int q = 0; q < 32; ++q) {
                    int n = nb * 32 + q;
                    float v = __uint_as_float(r[q]) + sepi[n];
                    v = fmaf(fl, sepi[256 + n], v);
                    v = fmaf(fi, sepi[512 + n], v);
                    v = fmaf(fe, sepi[768 + n], v);
                    v = fmaxf(v, 0.f);
                    sum = fmaf(v, sepi[1024 + n], sum);
                }
            }
            g_part[(size_t)blockIdx.y * NSPAN_PAD + m0 + tid] = sum;
        }
    }
    __syncthreads();
    if (tid == 0) { MBAR_INVAL(mbar0); MBAR_INVAL(mbar1); }
    __syncthreads();
    if (tid < 32) TC_DEALLOC(tmem, 512);

#else
    // ======================= SIMT fp32 fallback (two 128-wide halves) ==========
    __shared__ __align__(16) float sh[2304];
    float* As = sh;
    float* Bs = sh + 1024;

    int tid = threadIdx.x;
    int tx = tid % 16, ty = tid / 16;
    int m0 = blockIdx.x * 128;

    int lm, lkh;
    int xe = 0, yi = 0;
    float invlen = 0.f;
    int sA_ = 0;
    if (MODE == 2) {
        lm = tid & 127; lkh = tid >> 7;
        int s = m0 + lm; if (s >= NSPAN) s = NSPAN - 1;
        int i_ = g_si[s], j_ = g_sj[s];
        invlen = 1.0f / (float)(j_ - i_ + 1);
        xe = j_ + 1; yi = i_;
    } else {
        lm = tid >> 1; lkh = tid & 1;
        sA_ = m0 + lm; if (sA_ >= NSPAN) sA_ = NSPAN - 1;
    }

    int br = tid >> 5;
    int bc = (tid & 31) << 2;

    float rs_tot[8] = {};

    #pragma unroll 1
    for (int nh = 0; nh < 2; ++nh) {
        int n0 = blockIdx.y * 256 + nh * 128;

        float acc[8][8];
        #pragma unroll
        for (int a = 0; a < 8; ++a)
            #pragma unroll
            for (int b = 0; b < 8; ++b) acc[a][b] = 0.f;

        for (int kk = 0; kk < HDIM; kk += 8) {
            if (MODE == 2) {
                const float4 pe = *(const float4*)(g_P + (size_t)xe * HDIM + kk + lkh * 4);
                const float4 pi = *(const float4*)(g_P + (size_t)yi * HDIM + kk + lkh * 4);
                const float4 bb = *(const float4*)(bias1 + kk + lkh * 4);
                As[(lkh * 4 + 0) * 128 + lm] = fmaxf(fmaf(pe.x - pi.x, invlen, bb.x), 0.f);
                As[(lkh * 4 + 1) * 128 + lm] = fmaxf(fmaf(pe.y - pi.y, invlen, bb.y), 0.f);
                As[(lkh * 4 + 2) * 128 + lm] = fmaxf(fmaf(pe.z - pi.z, invlen, bb.z), 0.f);
                As[(lkh * 4 + 3) * 128 + lm] = fmaxf(fmaf(pe.w - pi.w, invlen, bb.w), 0.f);
            } else {
                const uint8_t* ar = g_h2f8 + (size_t)sA_ * HDIM + kk + lkh * 4;
                #pragma unroll
                for (int q = 0; q < 4; ++q) {
                    __nv_fp8_e4m3 f8 = *reinterpret_cast<const __nv_fp8_e4m3*>(ar + q);
                    As[(lkh * 4 + q) * 128 + lm] = float(f8) * H_INV;
                }
            }
            *(float4*)(Bs + br * 128 + bc) = *(const float4*)(W + (size_t)(kk + br) * HDIM + n0 + bc);
            __syncthreads();

            #pragma unroll
            for (int k = 0; k < 8; ++k) {
                float a[8], b[8];
                float4 t;
                t = *(const float4*)(As + k * 128 + (ty << 2));      a[0]=t.x; a[1]=t.y; a[2]=t.z; a[3]=t.w;
                t = *(const float4*)(As + k * 128 + (ty << 2) + 64); a[4]=t.x; a[5]=t.y; a[6]=t.z; a[7]=t.w;
                t = *(const float4*)(Bs + k * 128 + (tx << 2));      b[0]=t.x; b[1]=t.y; b[2]=t.z; b[3]=t.w;
                t = *(const float4*)(Bs + k * 128 + (tx << 2) + 64); b[4]=t.x; b[5]=t.y; b[6]=t.z; b[7]=t.w;
                #pragma unroll
                for (int ii = 0; ii < 8; ++ii)
                    #pragma unroll
                    for (int jj = 0; jj < 8; ++jj)
                        acc[ii][jj] = fmaf(a[ii], b[jj], acc[ii][jj]);
            }
            __syncthreads();
        }

        if (MODE == 2) {
            float cb[8];
            #pragma unroll
            for (int q = 0; q < 4; ++q) {
                cb[q]     = bias2[n0 + (tx << 2) + q];
                cb[4 + q] = bias2[n0 + (tx << 2) + 64 + q];
            }
            #pragma unroll
            for (int ri = 0; ri < 8; ++ri) {
                int r = (ri < 4) ? ((ty << 2) + ri) : (64 + (ty << 2) + ri - 4);
                int gs = m0 + r;
                if (gs < NSPAN) {
                    #pragma unroll
                    for (int q = 0; q < 4; ++q) {
                        __nv_fp8_e4m3 v0(fmaxf(acc[ri][q] + cb[q], 0.f) * H_SCALE);
                        __nv_fp8_e4m3 v1(fmaxf(acc[ri][4 + q] + cb[4 + q], 0.f) * H_SCALE);
                        g_h2f8[(size_t)gs * HDIM + n0 + (tx << 2) + q]      = *reinterpret_cast<uint8_t*>(&v0);
                        g_h2f8[(size_t)gs * HDIM + n0 + (tx << 2) + 64 + q] = *reinterpret_cast<uint8_t*>(&v1);
                    }
                }
            }
        } else {
            int cbase = n0 + (tx << 2);
            float cb[8], cl[8], ci[8], ce[8], cw[8];
            #pragma unroll
            for (int q = 0; q < 4; ++q) {
                int c0 = cbase + q, c1 = cbase + 64 + q;
                cb[q] = bias2[c0];             cb[4+q] = bias2[c1];
                cl[q] = g_wf[c0];              cl[4+q] = g_wf[c1];
                ci[q] = g_wf[HDIM + c0];       ci[4+q] = g_wf[HDIM + c1];
                ce[q] = g_wf[2*HDIM + c0];     ce[4+q] = g_wf[2*HDIM + c1];
                cw[q] = Ws2[c0];               cw[4+q] = Ws2[c1];
            }
            #pragma unroll
            for (int ri = 0; ri < 8; ++ri) {
                int r = (ri < 4) ? ((ty << 2) + ri) : (64 + (ty << 2) + ri - 4);
                int gs = m0 + r; int sc = (gs < NSPAN) ? gs : (NSPAN - 1);
                int ii_ = g_si[sc], jj_ = g_sj[sc];
                float fl = (float)(jj_ - ii_ + 1);
                float fi = (float)ii_;
                float fe = (float)(jj_ + 1);
                float sum = 0.f;
                #pragma unroll
                for (int cc = 0; cc < 8; ++cc) {
                    float v = acc[ri][cc] + cb[cc];
                    v = fmaf(fl, cl[cc], v);
                    v = fmaf(fi, ci[cc], v);
                    v = fmaf(fe, ce[cc], v);
                    v = fmaxf(v, 0.f);
                    sum = fmaf(v, cw[cc], sum);
                }
                rs_tot[ri] += sum;
            }
        }
    }

    if (MODE == 3) {
        #pragma unroll
        for (int ri = 0; ri < 8; ++ri) {
            int r = (ri < 4) ? ((ty << 2) + ri) : (64 + (ty << 2) + ri - 4);
            sh[r * 17 + tx] = rs_tot[ri];
        }
        __syncthreads();
        if (tid < 128) {
            float t = 0.f;
            #pragma unroll
            for (int q = 0; q < 16; ++q) t += sh[tid * 17 + q];
            g_part[(size_t)blockIdx.y * NSPAN_PAD + m0 + tid] = t;
        }
    }
#endif
}

// ---------------------------------------------------------------------------
// Final reduce (4 column-block partials)
// ---------------------------------------------------------------------------
__global__ void k_final(const float* __restrict__ b_s2, float* __restrict__ out)
{
    int s = blockIdx.x * blockDim.x + threadIdx.x;
    if (s < NSPAN) {
        float t = b_s2[0];
        #pragma unroll
        for (int q = 0; q < 4; ++q) t += g_part[(size_t)q * NSPAN_PAD + s];
        out[s] = t;
    }
}

// ---------------------------------------------------------------------------
extern "C" void kernel_launch(void* const* d_in, const int* in_sizes, int n_in,
                              void* d_out, int out_size)
{
    const int*   sent    = (const int*)d_in[0];
    const int*   pos     = (const int*)d_in[1];
    const float* We_wrd  = (const float*)d_in[2];
    const float* We_pos  = (const float*)d_in[3];
    const float* W_dan1  = (const float*)d_in[4];
    const float* b_dan1  = (const float*)d_in[5];
    const float* W_dan2  = (const float*)d_in[6];
    const float* b_dan2  = (const float*)d_in[7];
    const float* W_s1    = (const float*)d_in[8];
    const float* b_s1    = (const float*)d_in[9];
    const float* W_s2    = (const float*)d_in[10];
    const float* b_s2    = (const float*)d_in[11];
    float* out = (float*)d_out;

    uint8_t* wt2f8;  cudaGetSymbolAddress((void**)&wt2f8,  g_Wt2f8);
    uint8_t* ws1tf8; cudaGetSymbolAddress((void**)&ws1tf8, g_Ws1tf8);

    static bool attr_done = false;
    if (!attr_done) {
        cudaFuncSetAttribute((const void*)k_gemm_big<2>,
                             cudaFuncAttributeMaxDynamicSharedMemorySize, 98304);
        cudaFuncSetAttribute((const void*)k_gemm_big<3>,
                             cudaFuncAttributeMaxDynamicSharedMemorySize, 98304);
        attr_done = true;
    }

    k_pref <<<4, 256>>>(sent, pos, We_wrd, We_pos);
    k_spans<<<N_TOK, 256>>>();
    k_wfeat<<<4, 256>>>(W_s1);
    k_transp<<<dim3(32, 32), dim3(32, 8)>>>(W_dan2, wt2f8);
    k_transp<<<dim3(32, 32), dim3(32, 8)>>>(W_s1, ws1tf8);
    k_gemmP<<<dim3(7, 16), 256>>>(W_dan1);
    k_gemm_big<2><<<dim3(MTILES, 4), 256, 98304>>>(W_dan2, wt2f8,  b_dan1, b_dan2, nullptr);
    k_gemm_big<3><<<dim3(MTILES, 4), 256, 98304>>>(W_s1,   ws1tf8, nullptr, b_s1,  W_s2);
    k_final<<<(NSPAN + 255) / 256, 256>>>(b_s2, out);
}